// round 10
// baseline (speedup 1.0000x reference)
#include <cuda_runtime.h>
#include <cuda_bf16.h>
#include <cstdint>

// x: [16,4096,384] fp32 -> out [16,4096,384] fp32
// 8x8 window attention over 64x64 grid, 12 heads, hd=32.

#define TOKENS   65536
#define C_DIM    384
#define QKV_DIM  1152

__device__ __nv_bfloat16  g_qkvh[(size_t)TOKENS * QKV_DIM];   // qkv hi plane
__device__ __nv_bfloat16  g_qkvl[(size_t)TOKENS * QKV_DIM];   // qkv lo plane
__device__ __nv_bfloat16  g_ah [(size_t)TOKENS * C_DIM];
__device__ __nv_bfloat16  g_al [(size_t)TOKENS * C_DIM];
__device__ __nv_bfloat16  g_wqh[(size_t)C_DIM * QKV_DIM];
__device__ __nv_bfloat16  g_wql[(size_t)C_DIM * QKV_DIM];
__device__ __nv_bfloat16  g_wph[(size_t)C_DIM * C_DIM];
__device__ __nv_bfloat16  g_wpl[(size_t)C_DIM * C_DIM];

static __device__ __forceinline__ uint32_t smem_u32(const void* p) {
    return (uint32_t)__cvta_generic_to_shared(p);
}

#define CP_ASYNC16(smem, gptr) \
    asm volatile("cp.async.cg.shared.global [%0], [%1], 16;" :: "r"(smem), "l"(gptr))
#define CP_COMMIT() asm volatile("cp.async.commit_group;" ::: "memory")

#define MMA_BF16(d, a, b)                                                      \
    asm volatile(                                                              \
        "mma.sync.aligned.m16n8k16.row.col.f32.bf16.bf16.f32 "                 \
        "{%0,%1,%2,%3},{%4,%5,%6,%7},{%8,%9},{%0,%1,%2,%3};"                   \
        : "+f"(d[0]), "+f"(d[1]), "+f"(d[2]), "+f"(d[3])                       \
        : "r"(a[0]), "r"(a[1]), "r"(a[2]), "r"(a[3]), "r"(b[0]), "r"(b[1]))

// ---------------------------------------------------------------------------
// fp32 -> (hi, lo) bf16 split (weights only)
// ---------------------------------------------------------------------------
__global__ void split_kernel(const float* __restrict__ in,
                             __nv_bfloat16* __restrict__ hi,
                             __nv_bfloat16* __restrict__ lo, int n4)
{
    int i = blockIdx.x * blockDim.x + threadIdx.x;
    if (i >= n4) return;
    float4 v = ((const float4*)in)[i];
    __nv_bfloat16 h0 = __float2bfloat16(v.x), h1 = __float2bfloat16(v.y);
    __nv_bfloat16 h2 = __float2bfloat16(v.z), h3 = __float2bfloat16(v.w);
    __nv_bfloat162* hp = (__nv_bfloat162*)hi;
    __nv_bfloat162* lp = (__nv_bfloat162*)lo;
    hp[i*2]   = __nv_bfloat162(h0, h1);
    hp[i*2+1] = __nv_bfloat162(h2, h3);
    lp[i*2]   = __nv_bfloat162(__float2bfloat16(v.x - __bfloat162float(h0)),
                               __float2bfloat16(v.y - __bfloat162float(h1)));
    lp[i*2+1] = __nv_bfloat162(__float2bfloat16(v.z - __bfloat162float(h2)),
                               __float2bfloat16(v.w - __bfloat162float(h3)));
}

// ---------------------------------------------------------------------------
// Fused-split GEMM for QKV: A fp32 (x) split in-kernel; OUTPUT qkv as
// bf16 hi/lo planes (split done in epilogue, bit-identical to split_kernel).
// ---------------------------------------------------------------------------
#define FA_AF32   0
#define FA_AF32_ST 18432
#define FA_ABH    36864
#define FA_ABL    47104
#define FA_B      57344
#define FA_B_ST   17408
#define FA_BL_OFF 8704
#define FA_DYNSMEM 92160

__global__ __launch_bounds__(128, 2)
void gemm3_qkv_kernel(const float* __restrict__ A,
                      const __nv_bfloat16* __restrict__ Bh,
                      const __nv_bfloat16* __restrict__ Bl,
                      const float* __restrict__ bias,
                      __nv_bfloat16* __restrict__ Ch,
                      __nv_bfloat16* __restrict__ Cl, int N, int K)
{
    extern __shared__ char smem_raw[];
    const uint32_t sbase = smem_u32(smem_raw);

    const int tid  = threadIdx.x;
    const int lane = tid & 31;
    const int warp = tid >> 5;
    const int wm   = warp >> 1;
    const int wn   = warp & 1;
    const int m0   = blockIdx.y * 128;
    const int n0   = blockIdx.x * 128;
    const int KT   = K / 32;

    float acc[4][8][4];
    #pragma unroll
    for (int mi = 0; mi < 4; mi++)
        #pragma unroll
        for (int ni = 0; ni < 8; ni++)
            #pragma unroll
            for (int c = 0; c < 4; c++) acc[mi][ni][c] = 0.0f;

    uint32_t afo[8]; size_t afg[8];
    #pragma unroll
    for (int j = 0; j < 8; j++) {
        int idx = j * 128 + tid;
        int r = idx >> 3, c = idx & 7;
        afo[j] = (uint32_t)(r * 144 + c * 16);
        afg[j] = (size_t)r * K + c * 4;
    }
    uint32_t bso[4]; size_t bgo[4];
    #pragma unroll
    for (int j = 0; j < 4; j++) {
        int idx = j * 128 + tid;
        int br = idx >> 4, bc = idx & 15;
        bso[j] = (uint32_t)(br * 272 + bc * 16);
        bgo[j] = (size_t)br * N + bc * 8;
    }

    auto load_stage = [&](int kt, int st) {
        uint32_t ab = sbase + FA_AF32 + st * FA_AF32_ST;
        const float* pa = A + (size_t)m0 * K + kt * 32;
        #pragma unroll
        for (int j = 0; j < 8; j++) CP_ASYNC16(ab + afo[j], pa + afg[j]);
        uint32_t bb = sbase + FA_B + st * FA_B_ST;
        const __nv_bfloat16* pbh = Bh + (size_t)(kt * 32) * N + n0;
        const __nv_bfloat16* pbl = Bl + (size_t)(kt * 32) * N + n0;
        #pragma unroll
        for (int j = 0; j < 4; j++) CP_ASYNC16(bb + bso[j],             pbh + bgo[j]);
        #pragma unroll
        for (int j = 0; j < 4; j++) CP_ASYNC16(bb + FA_BL_OFF + bso[j], pbl + bgo[j]);
        CP_COMMIT();
    };

    load_stage(0, 0);

    for (int kt = 0; kt < KT; kt++) {
        const int st = kt & 1;
        asm volatile("cp.async.wait_group 0;" ::: "memory");
        __syncthreads();

        if (kt + 1 < KT) load_stage(kt + 1, st ^ 1);

        {
            const float* arow = (const float*)(smem_raw + FA_AF32 + st * FA_AF32_ST
                                               + tid * 144);
            __nv_bfloat16* hrow = (__nv_bfloat16*)(smem_raw + FA_ABH + tid * 80);
            __nv_bfloat16* lrow = (__nv_bfloat16*)(smem_raw + FA_ABL + tid * 80);
            #pragma unroll
            for (int j = 0; j < 8; j++) {
                float4 v = *(const float4*)(arow + j * 4);
                __nv_bfloat162 H0 = __floats2bfloat162_rn(v.x, v.y);
                __nv_bfloat162 H1 = __floats2bfloat162_rn(v.z, v.w);
                __nv_bfloat162 L0 = __floats2bfloat162_rn(v.x - __bfloat162float(H0.x),
                                                          v.y - __bfloat162float(H0.y));
                __nv_bfloat162 L1 = __floats2bfloat162_rn(v.z - __bfloat162float(H1.x),
                                                          v.w - __bfloat162float(H1.y));
                *(__nv_bfloat162*)(hrow + j * 4)     = H0;
                *(__nv_bfloat162*)(hrow + j * 4 + 2) = H1;
                *(__nv_bfloat162*)(lrow + j * 4)     = L0;
                *(__nv_bfloat162*)(lrow + j * 4 + 2) = L1;
            }
        }
        __syncthreads();

        const uint32_t bb = sbase + FA_B + st * FA_B_ST;
        #pragma unroll
        for (int kh = 0; kh < 2; kh++) {
            uint32_t bh[8][2], bl[8][2];
            const int brow = kh * 16 + (lane & 15);
            #pragma unroll
            for (int ni = 0; ni < 8; ni++) {
                uint32_t col2 = (uint32_t)((wn * 64 + ni * 8) * 2);
                uint32_t ad = bb + brow * 272 + col2;
                asm volatile("ldmatrix.sync.aligned.m8n8.x2.trans.shared.b16 {%0,%1},[%2];"
                             : "=r"(bh[ni][0]), "=r"(bh[ni][1]) : "r"(ad));
                ad = bb + FA_BL_OFF + brow * 272 + col2;
                asm volatile("ldmatrix.sync.aligned.m8n8.x2.trans.shared.b16 {%0,%1},[%2];"
                             : "=r"(bl[ni][0]), "=r"(bl[ni][1]) : "r"(ad));
            }
            #pragma unroll
            for (int mi = 0; mi < 4; mi++) {
                const int arow = wm * 64 + mi * 16 + ((lane >> 3) & 1) * 8 + (lane & 7);
                const int acol = kh * 16 + (lane >> 4) * 8;
                uint32_t Ahf[4], Alf[4];
                uint32_t ad = sbase + FA_ABH + arow * 80 + acol * 2;
                asm volatile("ldmatrix.sync.aligned.m8n8.x4.shared.b16 {%0,%1,%2,%3},[%4];"
                             : "=r"(Ahf[0]), "=r"(Ahf[1]), "=r"(Ahf[2]), "=r"(Ahf[3]) : "r"(ad));
                ad = sbase + FA_ABL + arow * 80 + acol * 2;
                asm volatile("ldmatrix.sync.aligned.m8n8.x4.shared.b16 {%0,%1,%2,%3},[%4];"
                             : "=r"(Alf[0]), "=r"(Alf[1]), "=r"(Alf[2]), "=r"(Alf[3]) : "r"(ad));
                #pragma unroll
                for (int ni = 0; ni < 8; ni++) MMA_BF16(acc[mi][ni], Ahf, bh[ni]);
                #pragma unroll
                for (int ni = 0; ni < 8; ni++) MMA_BF16(acc[mi][ni], Ahf, bl[ni]);
                #pragma unroll
                for (int ni = 0; ni < 8; ni++) MMA_BF16(acc[mi][ni], Alf, bh[ni]);
            }
        }
    }

    // Epilogue: bias + hi/lo bf16 split, write both planes.
    const int rbase = m0 + wm * 64 + (lane >> 2);
    const int cbase = n0 + wn * 64 + (lane & 3) * 2;
    #pragma unroll
    for (int ni = 0; ni < 8; ni++) {
        int c = cbase + ni * 8;
        float b0 = bias[c], b1 = bias[c + 1];
        #pragma unroll
        for (int mi = 0; mi < 4; mi++) {
            int r = rbase + mi * 16;
            #pragma unroll
            for (int h = 0; h < 2; h++) {
                float v0 = acc[mi][ni][h * 2 + 0] + b0;
                float v1 = acc[mi][ni][h * 2 + 1] + b1;
                __nv_bfloat162 H = __floats2bfloat162_rn(v0, v1);
                __nv_bfloat162 L = __floats2bfloat162_rn(v0 - __bfloat162float(H.x),
                                                         v1 - __bfloat162float(H.y));
                size_t off = (size_t)(r + h * 8) * N + c;
                *(__nv_bfloat162*)(Ch + off) = H;
                *(__nv_bfloat162*)(Cl + off) = L;
            }
        }
    }
}

// ---------------------------------------------------------------------------
// bf16-A 3x-split GEMM (proj): unchanged.
// ---------------------------------------------------------------------------
#define ST_AL 10240
#define ST_BH 20480
#define ST_BL 29184
#define ST_SZ 37888
#define N_STAGES 3
#define GEMM_DYNSMEM (N_STAGES * ST_SZ)

__global__ __launch_bounds__(128, 2)
void gemm3_kernel(const __nv_bfloat16* __restrict__ Ah,
                  const __nv_bfloat16* __restrict__ Al,
                  const __nv_bfloat16* __restrict__ Bh,
                  const __nv_bfloat16* __restrict__ Bl,
                  const float* __restrict__ bias,
                  float* __restrict__ C, int N, int K)
{
    extern __shared__ char smem_raw[];
    const uint32_t sbase = smem_u32(smem_raw);

    const int tid  = threadIdx.x;
    const int lane = tid & 31;
    const int warp = tid >> 5;
    const int wm   = warp >> 1;
    const int wn   = warp & 1;
    const int m0   = blockIdx.y * 128;
    const int n0   = blockIdx.x * 128;
    const int KT   = K / 32;

    float acc[4][8][4];
    #pragma unroll
    for (int mi = 0; mi < 4; mi++)
        #pragma unroll
        for (int ni = 0; ni < 8; ni++)
            #pragma unroll
            for (int c = 0; c < 4; c++) acc[mi][ni][c] = 0.0f;

    uint32_t aso[4]; size_t ago[4];
    uint32_t bso[4]; size_t bgo[4];
    #pragma unroll
    for (int j = 0; j < 4; j++) {
        int idx = j * 128 + tid;
        int ar = idx >> 2, ac = idx & 3;
        aso[j] = (uint32_t)(ar * 80 + ac * 16);
        ago[j] = (size_t)ar * K + ac * 8;
        int br = idx >> 4, bc = idx & 15;
        bso[j] = (uint32_t)(br * 272 + bc * 16);
        bgo[j] = (size_t)br * N + bc * 8;
    }

    auto load_stage = [&](int kt, int st) {
        uint32_t b = sbase + st * ST_SZ;
        const __nv_bfloat16* pah = Ah + (size_t)m0 * K + kt * 32;
        const __nv_bfloat16* pal = Al + (size_t)m0 * K + kt * 32;
        const __nv_bfloat16* pbh = Bh + (size_t)(kt * 32) * N + n0;
        const __nv_bfloat16* pbl = Bl + (size_t)(kt * 32) * N + n0;
        #pragma unroll
        for (int j = 0; j < 4; j++) CP_ASYNC16(b + aso[j],         pah + ago[j]);
        #pragma unroll
        for (int j = 0; j < 4; j++) CP_ASYNC16(b + ST_AL + aso[j], pal + ago[j]);
        #pragma unroll
        for (int j = 0; j < 4; j++) CP_ASYNC16(b + ST_BH + bso[j], pbh + bgo[j]);
        #pragma unroll
        for (int j = 0; j < 4; j++) CP_ASYNC16(b + ST_BL + bso[j], pbl + bgo[j]);
        CP_COMMIT();
    };

    load_stage(0, 0);
    load_stage(1, 1);

    int stage = 0;
    for (int kt = 0; kt < KT; kt++) {
        if (kt + 1 < KT) {
            asm volatile("cp.async.wait_group 1;" ::: "memory");
        } else {
            asm volatile("cp.async.wait_group 0;" ::: "memory");
        }
        __syncthreads();

        if (kt + 2 < KT) {
            int st2 = stage + 2; if (st2 >= N_STAGES) st2 -= N_STAGES;
            load_stage(kt + 2, st2);
        }

        const uint32_t b = sbase + stage * ST_SZ;
        #pragma unroll
        for (int kh = 0; kh < 2; kh++) {
            uint32_t bh[8][2], bl[8][2];
            const int brow = kh * 16 + (lane & 15);
            #pragma unroll
            for (int ni = 0; ni < 8; ni++) {
                uint32_t col2 = (uint32_t)((wn * 64 + ni * 8) * 2);
                uint32_t ad = b + ST_BH + brow * 272 + col2;
                asm volatile("ldmatrix.sync.aligned.m8n8.x2.trans.shared.b16 {%0,%1},[%2];"
                             : "=r"(bh[ni][0]), "=r"(bh[ni][1]) : "r"(ad));
                ad = b + ST_BL + brow * 272 + col2;
                asm volatile("ldmatrix.sync.aligned.m8n8.x2.trans.shared.b16 {%0,%1},[%2];"
                             : "=r"(bl[ni][0]), "=r"(bl[ni][1]) : "r"(ad));
            }
            #pragma unroll
            for (int mi = 0; mi < 4; mi++) {
                const int arow = wm * 64 + mi * 16 + ((lane >> 3) & 1) * 8 + (lane & 7);
                const int acol = kh * 16 + (lane >> 4) * 8;
                uint32_t Ahf[4], Alf[4];
                uint32_t ad = b + arow * 80 + acol * 2;
                asm volatile("ldmatrix.sync.aligned.m8n8.x4.shared.b16 {%0,%1,%2,%3},[%4];"
                             : "=r"(Ahf[0]), "=r"(Ahf[1]), "=r"(Ahf[2]), "=r"(Ahf[3]) : "r"(ad));
                ad = b + ST_AL + arow * 80 + acol * 2;
                asm volatile("ldmatrix.sync.aligned.m8n8.x4.shared.b16 {%0,%1,%2,%3},[%4];"
                             : "=r"(Alf[0]), "=r"(Alf[1]), "=r"(Alf[2]), "=r"(Alf[3]) : "r"(ad));
                #pragma unroll
                for (int ni = 0; ni < 8; ni++) MMA_BF16(acc[mi][ni], Ahf, bh[ni]);
                #pragma unroll
                for (int ni = 0; ni < 8; ni++) MMA_BF16(acc[mi][ni], Ahf, bl[ni]);
                #pragma unroll
                for (int ni = 0; ni < 8; ni++) MMA_BF16(acc[mi][ni], Alf, bh[ni]);
            }
        }
        stage++; if (stage >= N_STAGES) stage = 0;
    }

    const int rbase = m0 + wm * 64 + (lane >> 2);
    const int cbase = n0 + wn * 64 + (lane & 3) * 2;
    #pragma unroll
    for (int ni = 0; ni < 8; ni++) {
        int c = cbase + ni * 8;
        float b0 = 0.f, b1 = 0.f;
        if (bias) { b0 = bias[c]; b1 = bias[c + 1]; }
        #pragma unroll
        for (int mi = 0; mi < 4; mi++) {
            int r = rbase + mi * 16;
            *(float2*)(C + (size_t)r * N + c) =
                make_float2(acc[mi][ni][0] + b0, acc[mi][ni][1] + b1);
            *(float2*)(C + (size_t)(r + 8) * N + c) =
                make_float2(acc[mi][ni][2] + b0, acc[mi][ni][3] + b1);
        }
    }
}

// ---------------------------------------------------------------------------
// Tensor-core window attention: qkv hi/lo bf16 planes loaded straight into
// smem via cp.async (no conversion front-end).
// ---------------------------------------------------------------------------
__global__ __launch_bounds__(128)
void attn_tc_kernel(const __nv_bfloat16* __restrict__ qkvh,
                    const __nv_bfloat16* __restrict__ qkvl,
                    __nv_bfloat16* __restrict__ oh,
                    __nv_bfloat16* __restrict__ ol)
{
    __shared__ __nv_bfloat16 sQh[64][40], sQl[64][40];
    __shared__ __nv_bfloat16 sKh[64][40], sKl[64][40];
    __shared__ __nv_bfloat16 sVh[64][40], sVl[64][40];

    const int wx   = blockIdx.x;
    const int head = blockIdx.y;
    const int b  = wx >> 6;
    const int wi = wx & 63;
    const int wh = wi >> 3;
    const int wc = wi & 7;
    const int tid  = threadIdx.x;
    const int lane = tid & 31;
    const int warp = tid >> 5;

    // cp.async front-end: 6 planes x 64 tokens x 4 chunks = 1536 / 128 thr = 12
    {
        uint32_t dst[6] = {
            smem_u32(&sQh[0][0]), smem_u32(&sQl[0][0]),
            smem_u32(&sKh[0][0]), smem_u32(&sKl[0][0]),
            smem_u32(&sVh[0][0]), smem_u32(&sVl[0][0])
        };
        #pragma unroll
        for (int j = 0; j < 12; j++) {
            int f = j * 128 + tid;          // 0..1535
            int m = f >> 8;                 // plane 0..5
            int q = f & 255;
            int r = q >> 2;                 // token slot 0..63
            int c = q & 3;                  // 16B chunk in 64B head-slice
            int n = ((wh * 8 + (r >> 3)) << 6) + wc * 8 + (r & 7);
            const __nv_bfloat16* src = ((m & 1) ? qkvl : qkvh)
                + (size_t)(b * 4096 + n) * QKV_DIM + (m >> 1) * 384 + head * 32 + c * 8;
            CP_ASYNC16(dst[m] + (uint32_t)(r * 80 + c * 16), src);
        }
        CP_COMMIT();
    }
    asm volatile("cp.async.wait_group 0;" ::: "memory");
    __syncthreads();

    float cS[8][4];
    #pragma unroll
    for (int nt = 0; nt < 8; nt++)
        #pragma unroll
        for (int c = 0; c < 4; c++) cS[nt][c] = 0.0f;

    #pragma unroll
    for (int kt = 0; kt < 2; kt++) {
        const int arow = warp * 16 + ((lane >> 3) & 1) * 8 + (lane & 7);
        const int acol = kt * 16 + (lane >> 4) * 8;
        uint32_t qh[4], ql[4];
        uint32_t ad = smem_u32(&sQh[arow][acol]);
        asm volatile("ldmatrix.sync.aligned.m8n8.x4.shared.b16 {%0,%1,%2,%3},[%4];"
                     : "=r"(qh[0]), "=r"(qh[1]), "=r"(qh[2]), "=r"(qh[3]) : "r"(ad));
        ad = smem_u32(&sQl[arow][acol]);
        asm volatile("ldmatrix.sync.aligned.m8n8.x4.shared.b16 {%0,%1,%2,%3},[%4];"
                     : "=r"(ql[0]), "=r"(ql[1]), "=r"(ql[2]), "=r"(ql[3]) : "r"(ad));
        uint32_t kh2[8][2], kl2[8][2];
        #pragma unroll
        for (int nt = 0; nt < 8; nt++) {
            const int brow = nt * 8 + (lane & 7);
            const int bcol = kt * 16 + ((lane >> 3) & 1) * 8;
            uint32_t bd = smem_u32(&sKh[brow][bcol]);
            asm volatile("ldmatrix.sync.aligned.m8n8.x2.shared.b16 {%0,%1},[%2];"
                         : "=r"(kh2[nt][0]), "=r"(kh2[nt][1]) : "r"(bd));
            bd = smem_u32(&sKl[brow][bcol]);
            asm volatile("ldmatrix.sync.aligned.m8n8.x2.shared.b16 {%0,%1},[%2];"
                         : "=r"(kl2[nt][0]), "=r"(kl2[nt][1]) : "r"(bd));
        }
        #pragma unroll
        for (int nt = 0; nt < 8; nt++) MMA_BF16(cS[nt], qh, kh2[nt]);
        #pragma unroll
        for (int nt = 0; nt < 8; nt++) MMA_BF16(cS[nt], ql, kh2[nt]);
        #pragma unroll
        for (int nt = 0; nt < 8; nt++) MMA_BF16(cS[nt], qh, kl2[nt]);
    }

    const float scale = 0.17677669529663687f;
    {
        float m0 = -1e30f, m1 = -1e30f;
        #pragma unroll
        for (int nt = 0; nt < 8; nt++) {
            m0 = fmaxf(m0, fmaxf(cS[nt][0], cS[nt][1]));
            m1 = fmaxf(m1, fmaxf(cS[nt][2], cS[nt][3]));
        }
        m0 = fmaxf(m0, __shfl_xor_sync(0xffffffffu, m0, 1));
        m0 = fmaxf(m0, __shfl_xor_sync(0xffffffffu, m0, 2));
        m1 = fmaxf(m1, __shfl_xor_sync(0xffffffffu, m1, 1));
        m1 = fmaxf(m1, __shfl_xor_sync(0xffffffffu, m1, 2));
        float s0 = 0.f, s1 = 0.f;
        #pragma unroll
        for (int nt = 0; nt < 8; nt++) {
            cS[nt][0] = __expf((cS[nt][0] - m0) * scale); s0 += cS[nt][0];
            cS[nt][1] = __expf((cS[nt][1] - m0) * scale); s0 += cS[nt][1];
            cS[nt][2] = __expf((cS[nt][2] - m1) * scale); s1 += cS[nt][2];
            cS[nt][3] = __expf((cS[nt][3] - m1) * scale); s1 += cS[nt][3];
        }
        s0 += __shfl_xor_sync(0xffffffffu, s0, 1);
        s0 += __shfl_xor_sync(0xffffffffu, s0, 2);
        s1 += __shfl_xor_sync(0xffffffffu, s1, 1);
        s1 += __shfl_xor_sync(0xffffffffu, s1, 2);
        float i0 = 1.0f / s0, i1 = 1.0f / s1;
        #pragma unroll
        for (int nt = 0; nt < 8; nt++) {
            cS[nt][0] *= i0; cS[nt][1] *= i0;
            cS[nt][2] *= i1; cS[nt][3] *= i1;
        }
    }

    uint32_t ph[4][4], pl[4][4];
    #pragma unroll
    for (int kt = 0; kt < 4; kt++) {
        #pragma unroll
        for (int half = 0; half < 2; half++) {
            int nt = 2 * kt + half;
            __nv_bfloat162 H0 = __floats2bfloat162_rn(cS[nt][0], cS[nt][1]);
            __nv_bfloat162 H1 = __floats2bfloat162_rn(cS[nt][2], cS[nt][3]);
            __nv_bfloat162 L0 = __floats2bfloat162_rn(cS[nt][0] - __bfloat162float(H0.x),
                                                      cS[nt][1] - __bfloat162float(H0.y));
            __nv_bfloat162 L1 = __floats2bfloat162_rn(cS[nt][2] - __bfloat162float(H1.x),
                                                      cS[nt][3] - __bfloat162float(H1.y));
            ph[kt][half * 2 + 0] = *(uint32_t*)&H0;
            ph[kt][half * 2 + 1] = *(uint32_t*)&H1;
            pl[kt][half * 2 + 0] = *(uint32_t*)&L0;
            pl[kt][half * 2 + 1] = *(uint32_t*)&L1;
        }
    }

    float cO[4][4];
    #pragma unroll
    for (int nt = 0; nt < 4; nt++)
        #pragma unroll
        for (int c = 0; c < 4; c++) cO[nt][c] = 0.0f;

    #pragma unroll
    for (int kt = 0; kt < 4; kt++) {
        const int vrow = kt * 16 + (lane & 15);
        uint32_t vh2[4][2], vl2[4][2];
        #pragma unroll
        for (int nt = 0; nt < 4; nt++) {
            uint32_t ad = smem_u32(&sVh[vrow][nt * 8]);
            asm volatile("ldmatrix.sync.aligned.m8n8.x2.trans.shared.b16 {%0,%1},[%2];"
                         : "=r"(vh2[nt][0]), "=r"(vh2[nt][1]) : "r"(ad));
            ad = smem_u32(&sVl[vrow][nt * 8]);
            asm volatile("ldmatrix.sync.aligned.m8n8.x2.trans.shared.b16 {%0,%1},[%2];"
                         : "=r"(vl2[nt][0]), "=r"(vl2[nt][1]) : "r"(ad));
        }
        #pragma unroll
        for (int nt = 0; nt < 4; nt++) MMA_BF16(cO[nt], ph[kt], vh2[nt]);
        #pragma unroll
        for (int nt = 0; nt < 4; nt++) MMA_BF16(cO[nt], pl[kt], vh2[nt]);
        #pragma unroll
        for (int nt = 0; nt < 4; nt++) MMA_BF16(cO[nt], ph[kt], vl2[nt]);
    }

    {
        const int g0 = lane >> 2;
        const int c2 = (lane & 3) * 2;
        #pragma unroll
        for (int half = 0; half < 2; half++) {
            int r = warp * 16 + g0 + half * 8;
            int n = ((wh * 8 + (r >> 3)) << 6) + wc * 8 + (r & 7);
            size_t base = (size_t)(b * 4096 + n) * C_DIM + head * 32;
            #pragma unroll
            for (int nt = 0; nt < 4; nt++) {
                float v0 = cO[nt][half * 2 + 0];
                float v1 = cO[nt][half * 2 + 1];
                __nv_bfloat162 H = __floats2bfloat162_rn(v0, v1);
                __nv_bfloat162 L = __floats2bfloat162_rn(v0 - __bfloat162float(H.x),
                                                         v1 - __bfloat162float(H.y));
                size_t off = base + nt * 8 + c2;
                *(__nv_bfloat162*)(oh + off) = H;
                *(__nv_bfloat162*)(ol + off) = L;
            }
        }
    }
}

// ---------------------------------------------------------------------------
// Host launcher
// ---------------------------------------------------------------------------
extern "C" void kernel_launch(void* const* d_in, const int* in_sizes, int n_in,
                              void* d_out, int out_size)
{
    const float* x      = (const float*)d_in[0];
    const float* W_qkv  = (const float*)d_in[1];
    const float* b_qkv  = (const float*)d_in[2];
    const float* W_proj = (const float*)d_in[3];
    float* out = (float*)d_out;

    __nv_bfloat16 *qkvh, *qkvl, *ah, *al, *wqh, *wql, *wph, *wpl;
    cudaGetSymbolAddress((void**)&qkvh, g_qkvh);
    cudaGetSymbolAddress((void**)&qkvl, g_qkvl);
    cudaGetSymbolAddress((void**)&ah,  g_ah);
    cudaGetSymbolAddress((void**)&al,  g_al);
    cudaGetSymbolAddress((void**)&wqh, g_wqh);
    cudaGetSymbolAddress((void**)&wql, g_wql);
    cudaGetSymbolAddress((void**)&wph, g_wph);
    cudaGetSymbolAddress((void**)&wpl, g_wpl);

    cudaFuncSetAttribute(gemm3_kernel,
                         cudaFuncAttributeMaxDynamicSharedMemorySize, GEMM_DYNSMEM);
    cudaFuncSetAttribute(gemm3_qkv_kernel,
                         cudaFuncAttributeMaxDynamicSharedMemorySize, FA_DYNSMEM);

    // Weight splits only
    {
        int w4 = C_DIM * QKV_DIM / 4;
        split_kernel<<<(w4 + 255) / 256, 256>>>(W_qkv, wqh, wql, w4);
        int p4 = C_DIM * C_DIM / 4;
        split_kernel<<<(p4 + 255) / 256, 256>>>(W_proj, wph, wpl, p4);
    }
    // 1) QKV projection: fp32 A in-kernel split; qkv emitted as bf16 hi/lo
    {
        dim3 grid(QKV_DIM / 128, TOKENS / 128);
        gemm3_qkv_kernel<<<grid, 128, FA_DYNSMEM>>>(x, wqh, wql, b_qkv,
                                                    qkvh, qkvl, QKV_DIM, C_DIM);
    }
    // 2) Windowed attention (cp.async direct load of bf16 planes)
    {
        dim3 grid(1024, 12);
        attn_tc_kernel<<<grid, 128>>>(qkvh, qkvl, ah, al);
    }
    // 3) Output projection
    {
        dim3 grid(C_DIM / 128, TOKENS / 128);
        gemm3_kernel<<<grid, 128, GEMM_DYNSMEM>>>(ah, al, wph, wpl, nullptr, out,
                                                  C_DIM, C_DIM);
    }
}

// round 11
// speedup vs baseline: 1.1228x; 1.1228x over previous
#include <cuda_runtime.h>
#include <cuda_bf16.h>
#include <cstdint>

// x: [16,4096,384] fp32 -> out [16,4096,384] fp32
// 8x8 window attention over 64x64 grid, 12 heads, hd=32.

#define TOKENS   65536
#define C_DIM    384
#define QKV_DIM  1152

__device__ __nv_bfloat16  g_qkvh[(size_t)TOKENS * QKV_DIM];
__device__ __nv_bfloat16  g_qkvl[(size_t)TOKENS * QKV_DIM];
__device__ __nv_bfloat16  g_ah [(size_t)TOKENS * C_DIM];
__device__ __nv_bfloat16  g_al [(size_t)TOKENS * C_DIM];
__device__ __nv_bfloat16  g_wqh[(size_t)C_DIM * QKV_DIM];
__device__ __nv_bfloat16  g_wql[(size_t)C_DIM * QKV_DIM];
__device__ __nv_bfloat16  g_wph[(size_t)C_DIM * C_DIM];
__device__ __nv_bfloat16  g_wpl[(size_t)C_DIM * C_DIM];

static __device__ __forceinline__ uint32_t smem_u32(const void* p) {
    return (uint32_t)__cvta_generic_to_shared(p);
}

#define CP_ASYNC16(smem, gptr) \
    asm volatile("cp.async.cg.shared.global [%0], [%1], 16;" :: "r"(smem), "l"(gptr))
#define CP_COMMIT() asm volatile("cp.async.commit_group;" ::: "memory")

#define MMA_BF16(d, a, b)                                                      \
    asm volatile(                                                              \
        "mma.sync.aligned.m16n8k16.row.col.f32.bf16.bf16.f32 "                 \
        "{%0,%1,%2,%3},{%4,%5,%6,%7},{%8,%9},{%0,%1,%2,%3};"                   \
        : "+f"(d[0]), "+f"(d[1]), "+f"(d[2]), "+f"(d[3])                       \
        : "r"(a[0]), "r"(a[1]), "r"(a[2]), "r"(a[3]), "r"(b[0]), "r"(b[1]))

// ---------------------------------------------------------------------------
// fp32 -> (hi, lo) bf16 split (weights only)
// ---------------------------------------------------------------------------
__global__ void split_kernel(const float* __restrict__ in,
                             __nv_bfloat16* __restrict__ hi,
                             __nv_bfloat16* __restrict__ lo, int n4)
{
    int i = blockIdx.x * blockDim.x + threadIdx.x;
    if (i >= n4) return;
    float4 v = ((const float4*)in)[i];
    __nv_bfloat16 h0 = __float2bfloat16(v.x), h1 = __float2bfloat16(v.y);
    __nv_bfloat16 h2 = __float2bfloat16(v.z), h3 = __float2bfloat16(v.w);
    __nv_bfloat162* hp = (__nv_bfloat162*)hi;
    __nv_bfloat162* lp = (__nv_bfloat162*)lo;
    hp[i*2]   = __nv_bfloat162(h0, h1);
    hp[i*2+1] = __nv_bfloat162(h2, h3);
    lp[i*2]   = __nv_bfloat162(__float2bfloat16(v.x - __bfloat162float(h0)),
                               __float2bfloat16(v.y - __bfloat162float(h1)));
    lp[i*2+1] = __nv_bfloat162(__float2bfloat16(v.z - __bfloat162float(h2)),
                               __float2bfloat16(v.w - __bfloat162float(h3)));
}

// ---------------------------------------------------------------------------
// Fused-split GEMM for QKV: A fp32 split in-kernel; qkv emitted as bf16 hi/lo
// planes via SMEM-STAGED COALESCED epilogue (16B stores).
// ---------------------------------------------------------------------------
#define FA_AF32   0
#define FA_AF32_ST 18432
#define FA_ABH    36864
#define FA_ABL    47104
#define FA_B      57344
#define FA_B_ST   17408
#define FA_BL_OFF 8704
#define FA_DYNSMEM 92160

__global__ __launch_bounds__(128, 2)
void gemm3_qkv_kernel(const float* __restrict__ A,
                      const __nv_bfloat16* __restrict__ Bh,
                      const __nv_bfloat16* __restrict__ Bl,
                      const float* __restrict__ bias,
                      __nv_bfloat16* __restrict__ Ch,
                      __nv_bfloat16* __restrict__ Cl, int N, int K)
{
    extern __shared__ char smem_raw[];
    const uint32_t sbase = smem_u32(smem_raw);

    const int tid  = threadIdx.x;
    const int lane = tid & 31;
    const int warp = tid >> 5;
    const int wm   = warp >> 1;
    const int wn   = warp & 1;
    const int m0   = blockIdx.y * 128;
    const int n0   = blockIdx.x * 128;
    const int KT   = K / 32;

    float acc[4][8][4];
    #pragma unroll
    for (int mi = 0; mi < 4; mi++)
        #pragma unroll
        for (int ni = 0; ni < 8; ni++)
            #pragma unroll
            for (int c = 0; c < 4; c++) acc[mi][ni][c] = 0.0f;

    uint32_t afo[8]; size_t afg[8];
    #pragma unroll
    for (int j = 0; j < 8; j++) {
        int idx = j * 128 + tid;
        int r = idx >> 3, c = idx & 7;
        afo[j] = (uint32_t)(r * 144 + c * 16);
        afg[j] = (size_t)r * K + c * 4;
    }
    uint32_t bso[4]; size_t bgo[4];
    #pragma unroll
    for (int j = 0; j < 4; j++) {
        int idx = j * 128 + tid;
        int br = idx >> 4, bc = idx & 15;
        bso[j] = (uint32_t)(br * 272 + bc * 16);
        bgo[j] = (size_t)br * N + bc * 8;
    }

    auto load_stage = [&](int kt, int st) {
        uint32_t ab = sbase + FA_AF32 + st * FA_AF32_ST;
        const float* pa = A + (size_t)m0 * K + kt * 32;
        #pragma unroll
        for (int j = 0; j < 8; j++) CP_ASYNC16(ab + afo[j], pa + afg[j]);
        uint32_t bb = sbase + FA_B + st * FA_B_ST;
        const __nv_bfloat16* pbh = Bh + (size_t)(kt * 32) * N + n0;
        const __nv_bfloat16* pbl = Bl + (size_t)(kt * 32) * N + n0;
        #pragma unroll
        for (int j = 0; j < 4; j++) CP_ASYNC16(bb + bso[j],             pbh + bgo[j]);
        #pragma unroll
        for (int j = 0; j < 4; j++) CP_ASYNC16(bb + FA_BL_OFF + bso[j], pbl + bgo[j]);
        CP_COMMIT();
    };

    load_stage(0, 0);

    for (int kt = 0; kt < KT; kt++) {
        const int st = kt & 1;
        asm volatile("cp.async.wait_group 0;" ::: "memory");
        __syncthreads();

        if (kt + 1 < KT) load_stage(kt + 1, st ^ 1);

        {
            const float* arow = (const float*)(smem_raw + FA_AF32 + st * FA_AF32_ST
                                               + tid * 144);
            __nv_bfloat16* hrow = (__nv_bfloat16*)(smem_raw + FA_ABH + tid * 80);
            __nv_bfloat16* lrow = (__nv_bfloat16*)(smem_raw + FA_ABL + tid * 80);
            #pragma unroll
            for (int j = 0; j < 8; j++) {
                float4 v = *(const float4*)(arow + j * 4);
                __nv_bfloat162 H0 = __floats2bfloat162_rn(v.x, v.y);
                __nv_bfloat162 H1 = __floats2bfloat162_rn(v.z, v.w);
                __nv_bfloat162 L0 = __floats2bfloat162_rn(v.x - __bfloat162float(H0.x),
                                                          v.y - __bfloat162float(H0.y));
                __nv_bfloat162 L1 = __floats2bfloat162_rn(v.z - __bfloat162float(H1.x),
                                                          v.w - __bfloat162float(H1.y));
                *(__nv_bfloat162*)(hrow + j * 4)     = H0;
                *(__nv_bfloat162*)(hrow + j * 4 + 2) = H1;
                *(__nv_bfloat162*)(lrow + j * 4)     = L0;
                *(__nv_bfloat162*)(lrow + j * 4 + 2) = L1;
            }
        }
        __syncthreads();

        const uint32_t bb = sbase + FA_B + st * FA_B_ST;
        #pragma unroll
        for (int kh = 0; kh < 2; kh++) {
            uint32_t bh[8][2], bl[8][2];
            const int brow = kh * 16 + (lane & 15);
            #pragma unroll
            for (int ni = 0; ni < 8; ni++) {
                uint32_t col2 = (uint32_t)((wn * 64 + ni * 8) * 2);
                uint32_t ad = bb + brow * 272 + col2;
                asm volatile("ldmatrix.sync.aligned.m8n8.x2.trans.shared.b16 {%0,%1},[%2];"
                             : "=r"(bh[ni][0]), "=r"(bh[ni][1]) : "r"(ad));
                ad = bb + FA_BL_OFF + brow * 272 + col2;
                asm volatile("ldmatrix.sync.aligned.m8n8.x2.trans.shared.b16 {%0,%1},[%2];"
                             : "=r"(bl[ni][0]), "=r"(bl[ni][1]) : "r"(ad));
            }
            #pragma unroll
            for (int mi = 0; mi < 4; mi++) {
                const int arow = wm * 64 + mi * 16 + ((lane >> 3) & 1) * 8 + (lane & 7);
                const int acol = kh * 16 + (lane >> 4) * 8;
                uint32_t Ahf[4], Alf[4];
                uint32_t ad = sbase + FA_ABH + arow * 80 + acol * 2;
                asm volatile("ldmatrix.sync.aligned.m8n8.x4.shared.b16 {%0,%1,%2,%3},[%4];"
                             : "=r"(Ahf[0]), "=r"(Ahf[1]), "=r"(Ahf[2]), "=r"(Ahf[3]) : "r"(ad));
                ad = sbase + FA_ABL + arow * 80 + acol * 2;
                asm volatile("ldmatrix.sync.aligned.m8n8.x4.shared.b16 {%0,%1,%2,%3},[%4];"
                             : "=r"(Alf[0]), "=r"(Alf[1]), "=r"(Alf[2]), "=r"(Alf[3]) : "r"(ad));
                #pragma unroll
                for (int ni = 0; ni < 8; ni++) MMA_BF16(acc[mi][ni], Ahf, bh[ni]);
                #pragma unroll
                for (int ni = 0; ni < 8; ni++) MMA_BF16(acc[mi][ni], Ahf, bl[ni]);
                #pragma unroll
                for (int ni = 0; ni < 8; ni++) MMA_BF16(acc[mi][ni], Alf, bh[ni]);
            }
        }
    }

    // ---- Staged epilogue: per plane, fragments -> smem tile -> coalesced out.
    __syncthreads();   // release smem (mainloop fully done across warps)
    const int rb = wm * 64 + (lane >> 2);
    const int cb = wn * 64 + (lane & 3) * 2;
    #pragma unroll
    for (int plane = 0; plane < 2; plane++) {
        #pragma unroll
        for (int ni = 0; ni < 8; ni++) {
            int c = cb + ni * 8;
            float b0 = bias[n0 + c], b1 = bias[n0 + c + 1];
            #pragma unroll
            for (int mi = 0; mi < 4; mi++) {
                #pragma unroll
                for (int h = 0; h < 2; h++) {
                    int r = rb + mi * 16 + h * 8;
                    float v0 = acc[mi][ni][h * 2 + 0] + b0;
                    float v1 = acc[mi][ni][h * 2 + 1] + b1;
                    __nv_bfloat162 H = __floats2bfloat162_rn(v0, v1);
                    __nv_bfloat162 val = H;
                    if (plane) {
                        val = __floats2bfloat162_rn(v0 - __bfloat162float(H.x),
                                                    v1 - __bfloat162float(H.y));
                    }
                    *(__nv_bfloat162*)(smem_raw + r * 272 + c * 2) = val;
                }
            }
        }
        __syncthreads();
        __nv_bfloat16* Cp = plane ? Cl : Ch;
        #pragma unroll
        for (int j = 0; j < 16; j++) {
            int f = j * 128 + tid;      // 0..2047
            int r = f >> 4, ch = f & 15;
            uint4 v = *(const uint4*)(smem_raw + r * 272 + ch * 16);
            *(uint4*)(Cp + (size_t)(m0 + r) * N + n0 + ch * 8) = v;
        }
        __syncthreads();
    }
}

// ---------------------------------------------------------------------------
// bf16-A 3x-split GEMM (proj): unchanged.
// ---------------------------------------------------------------------------
#define ST_AL 10240
#define ST_BH 20480
#define ST_BL 29184
#define ST_SZ 37888
#define N_STAGES 3
#define GEMM_DYNSMEM (N_STAGES * ST_SZ)

__global__ __launch_bounds__(128, 2)
void gemm3_kernel(const __nv_bfloat16* __restrict__ Ah,
                  const __nv_bfloat16* __restrict__ Al,
                  const __nv_bfloat16* __restrict__ Bh,
                  const __nv_bfloat16* __restrict__ Bl,
                  const float* __restrict__ bias,
                  float* __restrict__ C, int N, int K)
{
    extern __shared__ char smem_raw[];
    const uint32_t sbase = smem_u32(smem_raw);

    const int tid  = threadIdx.x;
    const int lane = tid & 31;
    const int warp = tid >> 5;
    const int wm   = warp >> 1;
    const int wn   = warp & 1;
    const int m0   = blockIdx.y * 128;
    const int n0   = blockIdx.x * 128;
    const int KT   = K / 32;

    float acc[4][8][4];
    #pragma unroll
    for (int mi = 0; mi < 4; mi++)
        #pragma unroll
        for (int ni = 0; ni < 8; ni++)
            #pragma unroll
            for (int c = 0; c < 4; c++) acc[mi][ni][c] = 0.0f;

    uint32_t aso[4]; size_t ago[4];
    uint32_t bso[4]; size_t bgo[4];
    #pragma unroll
    for (int j = 0; j < 4; j++) {
        int idx = j * 128 + tid;
        int ar = idx >> 2, ac = idx & 3;
        aso[j] = (uint32_t)(ar * 80 + ac * 16);
        ago[j] = (size_t)ar * K + ac * 8;
        int br = idx >> 4, bc = idx & 15;
        bso[j] = (uint32_t)(br * 272 + bc * 16);
        bgo[j] = (size_t)br * N + bc * 8;
    }

    auto load_stage = [&](int kt, int st) {
        uint32_t b = sbase + st * ST_SZ;
        const __nv_bfloat16* pah = Ah + (size_t)m0 * K + kt * 32;
        const __nv_bfloat16* pal = Al + (size_t)m0 * K + kt * 32;
        const __nv_bfloat16* pbh = Bh + (size_t)(kt * 32) * N + n0;
        const __nv_bfloat16* pbl = Bl + (size_t)(kt * 32) * N + n0;
        #pragma unroll
        for (int j = 0; j < 4; j++) CP_ASYNC16(b + aso[j],         pah + ago[j]);
        #pragma unroll
        for (int j = 0; j < 4; j++) CP_ASYNC16(b + ST_AL + aso[j], pal + ago[j]);
        #pragma unroll
        for (int j = 0; j < 4; j++) CP_ASYNC16(b + ST_BH + bso[j], pbh + bgo[j]);
        #pragma unroll
        for (int j = 0; j < 4; j++) CP_ASYNC16(b + ST_BL + bso[j], pbl + bgo[j]);
        CP_COMMIT();
    };

    load_stage(0, 0);
    load_stage(1, 1);

    int stage = 0;
    for (int kt = 0; kt < KT; kt++) {
        if (kt + 1 < KT) {
            asm volatile("cp.async.wait_group 1;" ::: "memory");
        } else {
            asm volatile("cp.async.wait_group 0;" ::: "memory");
        }
        __syncthreads();

        if (kt + 2 < KT) {
            int st2 = stage + 2; if (st2 >= N_STAGES) st2 -= N_STAGES;
            load_stage(kt + 2, st2);
        }

        const uint32_t b = sbase + stage * ST_SZ;
        #pragma unroll
        for (int kh = 0; kh < 2; kh++) {
            uint32_t bh[8][2], bl[8][2];
            const int brow = kh * 16 + (lane & 15);
            #pragma unroll
            for (int ni = 0; ni < 8; ni++) {
                uint32_t col2 = (uint32_t)((wn * 64 + ni * 8) * 2);
                uint32_t ad = b + ST_BH + brow * 272 + col2;
                asm volatile("ldmatrix.sync.aligned.m8n8.x2.trans.shared.b16 {%0,%1},[%2];"
                             : "=r"(bh[ni][0]), "=r"(bh[ni][1]) : "r"(ad));
                ad = b + ST_BL + brow * 272 + col2;
                asm volatile("ldmatrix.sync.aligned.m8n8.x2.trans.shared.b16 {%0,%1},[%2];"
                             : "=r"(bl[ni][0]), "=r"(bl[ni][1]) : "r"(ad));
            }
            #pragma unroll
            for (int mi = 0; mi < 4; mi++) {
                const int arow = wm * 64 + mi * 16 + ((lane >> 3) & 1) * 8 + (lane & 7);
                const int acol = kh * 16 + (lane >> 4) * 8;
                uint32_t Ahf[4], Alf[4];
                uint32_t ad = b + arow * 80 + acol * 2;
                asm volatile("ldmatrix.sync.aligned.m8n8.x4.shared.b16 {%0,%1,%2,%3},[%4];"
                             : "=r"(Ahf[0]), "=r"(Ahf[1]), "=r"(Ahf[2]), "=r"(Ahf[3]) : "r"(ad));
                ad = b + ST_AL + arow * 80 + acol * 2;
                asm volatile("ldmatrix.sync.aligned.m8n8.x4.shared.b16 {%0,%1,%2,%3},[%4];"
                             : "=r"(Alf[0]), "=r"(Alf[1]), "=r"(Alf[2]), "=r"(Alf[3]) : "r"(ad));
                #pragma unroll
                for (int ni = 0; ni < 8; ni++) MMA_BF16(acc[mi][ni], Ahf, bh[ni]);
                #pragma unroll
                for (int ni = 0; ni < 8; ni++) MMA_BF16(acc[mi][ni], Ahf, bl[ni]);
                #pragma unroll
                for (int ni = 0; ni < 8; ni++) MMA_BF16(acc[mi][ni], Alf, bh[ni]);
            }
        }
        stage++; if (stage >= N_STAGES) stage = 0;
    }

    const int rbase = m0 + wm * 64 + (lane >> 2);
    const int cbase = n0 + wn * 64 + (lane & 3) * 2;
    #pragma unroll
    for (int ni = 0; ni < 8; ni++) {
        int c = cbase + ni * 8;
        float b0 = 0.f, b1 = 0.f;
        if (bias) { b0 = bias[c]; b1 = bias[c + 1]; }
        #pragma unroll
        for (int mi = 0; mi < 4; mi++) {
            int r = rbase + mi * 16;
            *(float2*)(C + (size_t)r * N + c) =
                make_float2(acc[mi][ni][0] + b0, acc[mi][ni][1] + b1);
            *(float2*)(C + (size_t)(r + 8) * N + c) =
                make_float2(acc[mi][ni][2] + b0, acc[mi][ni][3] + b1);
        }
    }
}

// ---------------------------------------------------------------------------
// Tensor-core window attention: cp.async bf16-plane loads; SMEM-STAGED
// coalesced output stores (64B per token per plane).
// ---------------------------------------------------------------------------
__global__ __launch_bounds__(128)
void attn_tc_kernel(const __nv_bfloat16* __restrict__ qkvh,
                    const __nv_bfloat16* __restrict__ qkvl,
                    __nv_bfloat16* __restrict__ oh,
                    __nv_bfloat16* __restrict__ ol)
{
    __shared__ __nv_bfloat16 sQh[64][40], sQl[64][40];
    __shared__ __nv_bfloat16 sKh[64][40], sKl[64][40];
    __shared__ __nv_bfloat16 sVh[64][40], sVl[64][40];

    const int wx   = blockIdx.x;
    const int head = blockIdx.y;
    const int b  = wx >> 6;
    const int wi = wx & 63;
    const int wh = wi >> 3;
    const int wc = wi & 7;
    const int tid  = threadIdx.x;
    const int lane = tid & 31;
    const int warp = tid >> 5;

    {
        uint32_t dst[6] = {
            smem_u32(&sQh[0][0]), smem_u32(&sQl[0][0]),
            smem_u32(&sKh[0][0]), smem_u32(&sKl[0][0]),
            smem_u32(&sVh[0][0]), smem_u32(&sVl[0][0])
        };
        #pragma unroll
        for (int j = 0; j < 12; j++) {
            int f = j * 128 + tid;
            int m = f >> 8;
            int q = f & 255;
            int r = q >> 2;
            int c = q & 3;
            int n = ((wh * 8 + (r >> 3)) << 6) + wc * 8 + (r & 7);
            const __nv_bfloat16* src = ((m & 1) ? qkvl : qkvh)
                + (size_t)(b * 4096 + n) * QKV_DIM + (m >> 1) * 384 + head * 32 + c * 8;
            CP_ASYNC16(dst[m] + (uint32_t)(r * 80 + c * 16), src);
        }
        CP_COMMIT();
    }
    asm volatile("cp.async.wait_group 0;" ::: "memory");
    __syncthreads();

    float cS[8][4];
    #pragma unroll
    for (int nt = 0; nt < 8; nt++)
        #pragma unroll
        for (int c = 0; c < 4; c++) cS[nt][c] = 0.0f;

    #pragma unroll
    for (int kt = 0; kt < 2; kt++) {
        const int arow = warp * 16 + ((lane >> 3) & 1) * 8 + (lane & 7);
        const int acol = kt * 16 + (lane >> 4) * 8;
        uint32_t qh[4], ql[4];
        uint32_t ad = smem_u32(&sQh[arow][acol]);
        asm volatile("ldmatrix.sync.aligned.m8n8.x4.shared.b16 {%0,%1,%2,%3},[%4];"
                     : "=r"(qh[0]), "=r"(qh[1]), "=r"(qh[2]), "=r"(qh[3]) : "r"(ad));
        ad = smem_u32(&sQl[arow][acol]);
        asm volatile("ldmatrix.sync.aligned.m8n8.x4.shared.b16 {%0,%1,%2,%3},[%4];"
                     : "=r"(ql[0]), "=r"(ql[1]), "=r"(ql[2]), "=r"(ql[3]) : "r"(ad));
        uint32_t kh2[8][2], kl2[8][2];
        #pragma unroll
        for (int nt = 0; nt < 8; nt++) {
            const int brow = nt * 8 + (lane & 7);
            const int bcol = kt * 16 + ((lane >> 3) & 1) * 8;
            uint32_t bd = smem_u32(&sKh[brow][bcol]);
            asm volatile("ldmatrix.sync.aligned.m8n8.x2.shared.b16 {%0,%1},[%2];"
                         : "=r"(kh2[nt][0]), "=r"(kh2[nt][1]) : "r"(bd));
            bd = smem_u32(&sKl[brow][bcol]);
            asm volatile("ldmatrix.sync.aligned.m8n8.x2.shared.b16 {%0,%1},[%2];"
                         : "=r"(kl2[nt][0]), "=r"(kl2[nt][1]) : "r"(bd));
        }
        #pragma unroll
        for (int nt = 0; nt < 8; nt++) MMA_BF16(cS[nt], qh, kh2[nt]);
        #pragma unroll
        for (int nt = 0; nt < 8; nt++) MMA_BF16(cS[nt], ql, kh2[nt]);
        #pragma unroll
        for (int nt = 0; nt < 8; nt++) MMA_BF16(cS[nt], qh, kl2[nt]);
    }

    const float scale = 0.17677669529663687f;
    {
        float m0 = -1e30f, m1 = -1e30f;
        #pragma unroll
        for (int nt = 0; nt < 8; nt++) {
            m0 = fmaxf(m0, fmaxf(cS[nt][0], cS[nt][1]));
            m1 = fmaxf(m1, fmaxf(cS[nt][2], cS[nt][3]));
        }
        m0 = fmaxf(m0, __shfl_xor_sync(0xffffffffu, m0, 1));
        m0 = fmaxf(m0, __shfl_xor_sync(0xffffffffu, m0, 2));
        m1 = fmaxf(m1, __shfl_xor_sync(0xffffffffu, m1, 1));
        m1 = fmaxf(m1, __shfl_xor_sync(0xffffffffu, m1, 2));
        float s0 = 0.f, s1 = 0.f;
        #pragma unroll
        for (int nt = 0; nt < 8; nt++) {
            cS[nt][0] = __expf((cS[nt][0] - m0) * scale); s0 += cS[nt][0];
            cS[nt][1] = __expf((cS[nt][1] - m0) * scale); s0 += cS[nt][1];
            cS[nt][2] = __expf((cS[nt][2] - m1) * scale); s1 += cS[nt][2];
            cS[nt][3] = __expf((cS[nt][3] - m1) * scale); s1 += cS[nt][3];
        }
        s0 += __shfl_xor_sync(0xffffffffu, s0, 1);
        s0 += __shfl_xor_sync(0xffffffffu, s0, 2);
        s1 += __shfl_xor_sync(0xffffffffu, s1, 1);
        s1 += __shfl_xor_sync(0xffffffffu, s1, 2);
        float i0 = 1.0f / s0, i1 = 1.0f / s1;
        #pragma unroll
        for (int nt = 0; nt < 8; nt++) {
            cS[nt][0] *= i0; cS[nt][1] *= i0;
            cS[nt][2] *= i1; cS[nt][3] *= i1;
        }
    }

    uint32_t ph[4][4], pl[4][4];
    #pragma unroll
    for (int kt = 0; kt < 4; kt++) {
        #pragma unroll
        for (int half = 0; half < 2; half++) {
            int nt = 2 * kt + half;
            __nv_bfloat162 H0 = __floats2bfloat162_rn(cS[nt][0], cS[nt][1]);
            __nv_bfloat162 H1 = __floats2bfloat162_rn(cS[nt][2], cS[nt][3]);
            __nv_bfloat162 L0 = __floats2bfloat162_rn(cS[nt][0] - __bfloat162float(H0.x),
                                                      cS[nt][1] - __bfloat162float(H0.y));
            __nv_bfloat162 L1 = __floats2bfloat162_rn(cS[nt][2] - __bfloat162float(H1.x),
                                                      cS[nt][3] - __bfloat162float(H1.y));
            ph[kt][half * 2 + 0] = *(uint32_t*)&H0;
            ph[kt][half * 2 + 1] = *(uint32_t*)&H1;
            pl[kt][half * 2 + 0] = *(uint32_t*)&L0;
            pl[kt][half * 2 + 1] = *(uint32_t*)&L1;
        }
    }

    float cO[4][4];
    #pragma unroll
    for (int nt = 0; nt < 4; nt++)
        #pragma unroll
        for (int c = 0; c < 4; c++) cO[nt][c] = 0.0f;

    #pragma unroll
    for (int kt = 0; kt < 4; kt++) {
        const int vrow = kt * 16 + (lane & 15);
        uint32_t vh2[4][2], vl2[4][2];
        #pragma unroll
        for (int nt = 0; nt < 4; nt++) {
            uint32_t ad = smem_u32(&sVh[vrow][nt * 8]);
            asm volatile("ldmatrix.sync.aligned.m8n8.x2.trans.shared.b16 {%0,%1},[%2];"
                         : "=r"(vh2[nt][0]), "=r"(vh2[nt][1]) : "r"(ad));
            ad = smem_u32(&sVl[vrow][nt * 8]);
            asm volatile("ldmatrix.sync.aligned.m8n8.x2.trans.shared.b16 {%0,%1},[%2];"
                         : "=r"(vl2[nt][0]), "=r"(vl2[nt][1]) : "r"(ad));
        }
        #pragma unroll
        for (int nt = 0; nt < 4; nt++) MMA_BF16(cO[nt], ph[kt], vh2[nt]);
        #pragma unroll
        for (int nt = 0; nt < 4; nt++) MMA_BF16(cO[nt], pl[kt], vh2[nt]);
        #pragma unroll
        for (int nt = 0; nt < 4; nt++) MMA_BF16(cO[nt], ph[kt], vl2[nt]);
    }

    // Staged output: fragments -> sQh/sQl (reused), then coalesced 16B stores.
    __syncthreads();   // all warps done reading Q/V smem
    {
        const int g0 = lane >> 2;
        const int c2 = (lane & 3) * 2;
        #pragma unroll
        for (int half = 0; half < 2; half++) {
            int r = warp * 16 + g0 + half * 8;
            #pragma unroll
            for (int nt = 0; nt < 4; nt++) {
                float v0 = cO[nt][half * 2 + 0];
                float v1 = cO[nt][half * 2 + 1];
                __nv_bfloat162 H = __floats2bfloat162_rn(v0, v1);
                __nv_bfloat162 L = __floats2bfloat162_rn(v0 - __bfloat162float(H.x),
                                                         v1 - __bfloat162float(H.y));
                *(__nv_bfloat162*)&sQh[r][nt * 8 + c2] = H;
                *(__nv_bfloat162*)&sQl[r][nt * 8 + c2] = L;
            }
        }
    }
    __syncthreads();
    {
        #pragma unroll
        for (int j = 0; j < 4; j++) {
            int f = j * 128 + tid;        // 0..511
            int p = f >> 8;               // plane
            int q = f & 255;
            int r = q >> 2;               // token slot
            int ch = q & 3;               // 16B chunk of 64B row
            int n = ((wh * 8 + (r >> 3)) << 6) + wc * 8 + (r & 7);
            size_t base = (size_t)(b * 4096 + n) * C_DIM + head * 32 + ch * 8;
            uint4 v = p ? *(const uint4*)&sQl[r][ch * 8]
                        : *(const uint4*)&sQh[r][ch * 8];
            *(uint4*)((p ? ol : oh) + base) = v;
        }
    }
}

// ---------------------------------------------------------------------------
// Host launcher
// ---------------------------------------------------------------------------
extern "C" void kernel_launch(void* const* d_in, const int* in_sizes, int n_in,
                              void* d_out, int out_size)
{
    const float* x      = (const float*)d_in[0];
    const float* W_qkv  = (const float*)d_in[1];
    const float* b_qkv  = (const float*)d_in[2];
    const float* W_proj = (const float*)d_in[3];
    float* out = (float*)d_out;

    __nv_bfloat16 *qkvh, *qkvl, *ah, *al, *wqh, *wql, *wph, *wpl;
    cudaGetSymbolAddress((void**)&qkvh, g_qkvh);
    cudaGetSymbolAddress((void**)&qkvl, g_qkvl);
    cudaGetSymbolAddress((void**)&ah,  g_ah);
    cudaGetSymbolAddress((void**)&al,  g_al);
    cudaGetSymbolAddress((void**)&wqh, g_wqh);
    cudaGetSymbolAddress((void**)&wql, g_wql);
    cudaGetSymbolAddress((void**)&wph, g_wph);
    cudaGetSymbolAddress((void**)&wpl, g_wpl);

    cudaFuncSetAttribute(gemm3_kernel,
                         cudaFuncAttributeMaxDynamicSharedMemorySize, GEMM_DYNSMEM);
    cudaFuncSetAttribute(gemm3_qkv_kernel,
                         cudaFuncAttributeMaxDynamicSharedMemorySize, FA_DYNSMEM);

    {
        int w4 = C_DIM * QKV_DIM / 4;
        split_kernel<<<(w4 + 255) / 256, 256>>>(W_qkv, wqh, wql, w4);
        int p4 = C_DIM * C_DIM / 4;
        split_kernel<<<(p4 + 255) / 256, 256>>>(W_proj, wph, wpl, p4);
    }
    {
        dim3 grid(QKV_DIM / 128, TOKENS / 128);
        gemm3_qkv_kernel<<<grid, 128, FA_DYNSMEM>>>(x, wqh, wql, b_qkv,
                                                    qkvh, qkvl, QKV_DIM, C_DIM);
    }
    {
        dim3 grid(1024, 12);
        attn_tc_kernel<<<grid, 128>>>(qkvh, qkvl, ah, al);
    }
    {
        dim3 grid(C_DIM / 128, TOKENS / 128);
        gemm3_kernel<<<grid, 128, GEMM_DYNSMEM>>>(ah, al, wph, wpl, nullptr, out,
                                                  C_DIM, C_DIM);
    }
}

// round 12
// speedup vs baseline: 1.3492x; 1.2016x over previous
#include <cuda_runtime.h>
#include <cuda_fp16.h>
#include <cstdint>

// x: [16,4096,384] fp32 -> out [16,4096,384] fp32
// 8x8 window attention over 64x64 grid, 12 heads, hd=32.
// Precision scheme: fp16. GEMMs 2-term (weights hi/lo split, activations
// single-rounded). Attention internally 3-term (qkv + P as hi/lo).

#define TOKENS   65536
#define C_DIM    384
#define QKV_DIM  1152

__device__ __half  g_qkvh[(size_t)TOKENS * QKV_DIM];
__device__ __half  g_qkvl[(size_t)TOKENS * QKV_DIM];
__device__ __half  g_ao  [(size_t)TOKENS * C_DIM];     // attn out, single plane
__device__ __half  g_wqh [(size_t)C_DIM * QKV_DIM];
__device__ __half  g_wql [(size_t)C_DIM * QKV_DIM];
__device__ __half  g_wph [(size_t)C_DIM * C_DIM];
__device__ __half  g_wpl [(size_t)C_DIM * C_DIM];

static __device__ __forceinline__ uint32_t smem_u32(const void* p) {
    return (uint32_t)__cvta_generic_to_shared(p);
}

#define CP_ASYNC16(smem, gptr) \
    asm volatile("cp.async.cg.shared.global [%0], [%1], 16;" :: "r"(smem), "l"(gptr))
#define CP_COMMIT() asm volatile("cp.async.commit_group;" ::: "memory")

#define MMA_F16(d, a, b)                                                       \
    asm volatile(                                                              \
        "mma.sync.aligned.m16n8k16.row.col.f32.f16.f16.f32 "                   \
        "{%0,%1,%2,%3},{%4,%5,%6,%7},{%8,%9},{%0,%1,%2,%3};"                   \
        : "+f"(d[0]), "+f"(d[1]), "+f"(d[2]), "+f"(d[3])                       \
        : "r"(a[0]), "r"(a[1]), "r"(a[2]), "r"(a[3]), "r"(b[0]), "r"(b[1]))

// ---------------------------------------------------------------------------
// fp32 -> (hi, lo) fp16 split (weights)
// ---------------------------------------------------------------------------
__global__ void split_kernel(const float* __restrict__ in,
                             __half* __restrict__ hi,
                             __half* __restrict__ lo, int n4)
{
    int i = blockIdx.x * blockDim.x + threadIdx.x;
    if (i >= n4) return;
    float4 v = ((const float4*)in)[i];
    __half h0 = __float2half_rn(v.x), h1 = __float2half_rn(v.y);
    __half h2 = __float2half_rn(v.z), h3 = __float2half_rn(v.w);
    __half2* hp = (__half2*)hi;
    __half2* lp = (__half2*)lo;
    hp[i*2]   = __halves2half2(h0, h1);
    hp[i*2+1] = __halves2half2(h2, h3);
    lp[i*2]   = __halves2half2(__float2half_rn(v.x - __half2float(h0)),
                               __float2half_rn(v.y - __half2float(h1)));
    lp[i*2+1] = __halves2half2(__float2half_rn(v.z - __half2float(h2)),
                               __float2half_rn(v.w - __half2float(h3)));
}

// ---------------------------------------------------------------------------
// Fused QKV GEMM: A fp32 -> single fp16 in-kernel; C = Ah@(Bh+Bl) + bias.
// Output: qkv as fp16 hi/lo planes (staged, coalesced stores).
// CTA 128x128, 4 warps (2x2), warp 64x64, BK=32, 2-stage cp.async.
// smem: AF32 2x18432 @0 | AH (single) 10240 @36864 | B 2x17408 @47104
// ---------------------------------------------------------------------------
#define FA_AF32   0
#define FA_AF32_ST 18432
#define FA_AH     36864
#define FA_B      47104
#define FA_B_ST   17408
#define FA_BL_OFF 8704
#define FA_DYNSMEM 81920

__global__ __launch_bounds__(128, 2)
void gemm_qkv_kernel(const float* __restrict__ A,
                     const __half* __restrict__ Bh,
                     const __half* __restrict__ Bl,
                     const float* __restrict__ bias,
                     __half* __restrict__ Ch,
                     __half* __restrict__ Cl, int N, int K)
{
    extern __shared__ char smem_raw[];
    const uint32_t sbase = smem_u32(smem_raw);

    const int tid  = threadIdx.x;
    const int lane = tid & 31;
    const int warp = tid >> 5;
    const int wm   = warp >> 1;
    const int wn   = warp & 1;
    const int m0   = blockIdx.y * 128;
    const int n0   = blockIdx.x * 128;
    const int KT   = K / 32;

    float acc[4][8][4];
    #pragma unroll
    for (int mi = 0; mi < 4; mi++)
        #pragma unroll
        for (int ni = 0; ni < 8; ni++)
            #pragma unroll
            for (int c = 0; c < 4; c++) acc[mi][ni][c] = 0.0f;

    uint32_t afo[8]; size_t afg[8];
    #pragma unroll
    for (int j = 0; j < 8; j++) {
        int idx = j * 128 + tid;
        int r = idx >> 3, c = idx & 7;
        afo[j] = (uint32_t)(r * 144 + c * 16);
        afg[j] = (size_t)r * K + c * 4;
    }
    uint32_t bso[4]; size_t bgo[4];
    #pragma unroll
    for (int j = 0; j < 4; j++) {
        int idx = j * 128 + tid;
        int br = idx >> 4, bc = idx & 15;
        bso[j] = (uint32_t)(br * 272 + bc * 16);
        bgo[j] = (size_t)br * N + bc * 8;
    }

    auto load_stage = [&](int kt, int st) {
        uint32_t ab = sbase + FA_AF32 + st * FA_AF32_ST;
        const float* pa = A + (size_t)m0 * K + kt * 32;
        #pragma unroll
        for (int j = 0; j < 8; j++) CP_ASYNC16(ab + afo[j], pa + afg[j]);
        uint32_t bb = sbase + FA_B + st * FA_B_ST;
        const __half* pbh = Bh + (size_t)(kt * 32) * N + n0;
        const __half* pbl = Bl + (size_t)(kt * 32) * N + n0;
        #pragma unroll
        for (int j = 0; j < 4; j++) CP_ASYNC16(bb + bso[j],             pbh + bgo[j]);
        #pragma unroll
        for (int j = 0; j < 4; j++) CP_ASYNC16(bb + FA_BL_OFF + bso[j], pbl + bgo[j]);
        CP_COMMIT();
    };

    load_stage(0, 0);

    for (int kt = 0; kt < KT; kt++) {
        const int st = kt & 1;
        asm volatile("cp.async.wait_group 0;" ::: "memory");
        __syncthreads();

        if (kt + 1 < KT) load_stage(kt + 1, st ^ 1);

        // Convert A fp32 -> single fp16 buffer (row = tid)
        {
            const float* arow = (const float*)(smem_raw + FA_AF32 + st * FA_AF32_ST
                                               + tid * 144);
            __half* hrow = (__half*)(smem_raw + FA_AH + tid * 80);
            #pragma unroll
            for (int j = 0; j < 8; j++) {
                float4 v = *(const float4*)(arow + j * 4);
                *(__half2*)(hrow + j * 4)     = __floats2half2_rn(v.x, v.y);
                *(__half2*)(hrow + j * 4 + 2) = __floats2half2_rn(v.z, v.w);
            }
        }
        __syncthreads();

        const uint32_t bb = sbase + FA_B + st * FA_B_ST;
        #pragma unroll
        for (int kh = 0; kh < 2; kh++) {
            uint32_t bh[8][2], bl[8][2];
            const int brow = kh * 16 + (lane & 15);
            #pragma unroll
            for (int ni = 0; ni < 8; ni++) {
                uint32_t col2 = (uint32_t)((wn * 64 + ni * 8) * 2);
                uint32_t ad = bb + brow * 272 + col2;
                asm volatile("ldmatrix.sync.aligned.m8n8.x2.trans.shared.b16 {%0,%1},[%2];"
                             : "=r"(bh[ni][0]), "=r"(bh[ni][1]) : "r"(ad));
                ad = bb + FA_BL_OFF + brow * 272 + col2;
                asm volatile("ldmatrix.sync.aligned.m8n8.x2.trans.shared.b16 {%0,%1},[%2];"
                             : "=r"(bl[ni][0]), "=r"(bl[ni][1]) : "r"(ad));
            }
            #pragma unroll
            for (int mi = 0; mi < 4; mi++) {
                const int arow = wm * 64 + mi * 16 + ((lane >> 3) & 1) * 8 + (lane & 7);
                const int acol = kh * 16 + (lane >> 4) * 8;
                uint32_t Ahf[4];
                uint32_t ad = sbase + FA_AH + arow * 80 + acol * 2;
                asm volatile("ldmatrix.sync.aligned.m8n8.x4.shared.b16 {%0,%1,%2,%3},[%4];"
                             : "=r"(Ahf[0]), "=r"(Ahf[1]), "=r"(Ahf[2]), "=r"(Ahf[3]) : "r"(ad));
                #pragma unroll
                for (int ni = 0; ni < 8; ni++) MMA_F16(acc[mi][ni], Ahf, bh[ni]);
                #pragma unroll
                for (int ni = 0; ni < 8; ni++) MMA_F16(acc[mi][ni], Ahf, bl[ni]);
            }
        }
    }

    // Staged epilogue: per plane -> smem tile -> coalesced 16B stores.
    __syncthreads();
    const int rb = wm * 64 + (lane >> 2);
    const int cb = wn * 64 + (lane & 3) * 2;
    #pragma unroll
    for (int plane = 0; plane < 2; plane++) {
        #pragma unroll
        for (int ni = 0; ni < 8; ni++) {
            int c = cb + ni * 8;
            float b0 = bias[n0 + c], b1 = bias[n0 + c + 1];
            #pragma unroll
            for (int mi = 0; mi < 4; mi++) {
                #pragma unroll
                for (int h = 0; h < 2; h++) {
                    int r = rb + mi * 16 + h * 8;
                    float v0 = acc[mi][ni][h * 2 + 0] + b0;
                    float v1 = acc[mi][ni][h * 2 + 1] + b1;
                    __half2 H = __floats2half2_rn(v0, v1);
                    __half2 val = H;
                    if (plane) {
                        val = __floats2half2_rn(v0 - __half2float(__low2half(H)),
                                                v1 - __half2float(__high2half(H)));
                    }
                    *(__half2*)(smem_raw + r * 272 + c * 2) = val;
                }
            }
        }
        __syncthreads();
        __half* Cp = plane ? Cl : Ch;
        #pragma unroll
        for (int j = 0; j < 16; j++) {
            int f = j * 128 + tid;
            int r = f >> 4, ch = f & 15;
            uint4 v = *(const uint4*)(smem_raw + r * 272 + ch * 16);
            *(uint4*)(Cp + (size_t)(m0 + r) * N + n0 + ch * 8) = v;
        }
        __syncthreads();
    }
}

// ---------------------------------------------------------------------------
// Proj GEMM: A single fp16 plane, B hi/lo, 2-term; fp32 out.
// smem per stage: A 10240 | Bh 8704 | Bl 8704 = 27648; 3 stages.
// ---------------------------------------------------------------------------
#define P_BH 10240
#define P_BL 18944
#define P_ST 27648
#define P_NSTAGES 3
#define PROJ_DYNSMEM (P_NSTAGES * P_ST)

__global__ __launch_bounds__(128, 2)
void gemm_proj_kernel(const __half* __restrict__ Ah,
                      const __half* __restrict__ Bh,
                      const __half* __restrict__ Bl,
                      float* __restrict__ C, int N, int K)
{
    extern __shared__ char smem_raw[];
    const uint32_t sbase = smem_u32(smem_raw);

    const int tid  = threadIdx.x;
    const int lane = tid & 31;
    const int warp = tid >> 5;
    const int wm   = warp >> 1;
    const int wn   = warp & 1;
    const int m0   = blockIdx.y * 128;
    const int n0   = blockIdx.x * 128;
    const int KT   = K / 32;

    float acc[4][8][4];
    #pragma unroll
    for (int mi = 0; mi < 4; mi++)
        #pragma unroll
        for (int ni = 0; ni < 8; ni++)
            #pragma unroll
            for (int c = 0; c < 4; c++) acc[mi][ni][c] = 0.0f;

    uint32_t aso[4]; size_t ago[4];
    uint32_t bso[4]; size_t bgo[4];
    #pragma unroll
    for (int j = 0; j < 4; j++) {
        int idx = j * 128 + tid;
        int ar = idx >> 2, ac = idx & 3;
        aso[j] = (uint32_t)(ar * 80 + ac * 16);
        ago[j] = (size_t)ar * K + ac * 8;
        int br = idx >> 4, bc = idx & 15;
        bso[j] = (uint32_t)(br * 272 + bc * 16);
        bgo[j] = (size_t)br * N + bc * 8;
    }

    auto load_stage = [&](int kt, int st) {
        uint32_t b = sbase + st * P_ST;
        const __half* pa  = Ah + (size_t)m0 * K + kt * 32;
        const __half* pbh = Bh + (size_t)(kt * 32) * N + n0;
        const __half* pbl = Bl + (size_t)(kt * 32) * N + n0;
        #pragma unroll
        for (int j = 0; j < 4; j++) CP_ASYNC16(b + aso[j],        pa  + ago[j]);
        #pragma unroll
        for (int j = 0; j < 4; j++) CP_ASYNC16(b + P_BH + bso[j], pbh + bgo[j]);
        #pragma unroll
        for (int j = 0; j < 4; j++) CP_ASYNC16(b + P_BL + bso[j], pbl + bgo[j]);
        CP_COMMIT();
    };

    load_stage(0, 0);
    load_stage(1, 1);

    int stage = 0;
    for (int kt = 0; kt < KT; kt++) {
        if (kt + 1 < KT) {
            asm volatile("cp.async.wait_group 1;" ::: "memory");
        } else {
            asm volatile("cp.async.wait_group 0;" ::: "memory");
        }
        __syncthreads();

        if (kt + 2 < KT) {
            int st2 = stage + 2; if (st2 >= P_NSTAGES) st2 -= P_NSTAGES;
            load_stage(kt + 2, st2);
        }

        const uint32_t b = sbase + stage * P_ST;
        #pragma unroll
        for (int kh = 0; kh < 2; kh++) {
            uint32_t bh[8][2], bl[8][2];
            const int brow = kh * 16 + (lane & 15);
            #pragma unroll
            for (int ni = 0; ni < 8; ni++) {
                uint32_t col2 = (uint32_t)((wn * 64 + ni * 8) * 2);
                uint32_t ad = b + P_BH + brow * 272 + col2;
                asm volatile("ldmatrix.sync.aligned.m8n8.x2.trans.shared.b16 {%0,%1},[%2];"
                             : "=r"(bh[ni][0]), "=r"(bh[ni][1]) : "r"(ad));
                ad = b + P_BL + brow * 272 + col2;
                asm volatile("ldmatrix.sync.aligned.m8n8.x2.trans.shared.b16 {%0,%1},[%2];"
                             : "=r"(bl[ni][0]), "=r"(bl[ni][1]) : "r"(ad));
            }
            #pragma unroll
            for (int mi = 0; mi < 4; mi++) {
                const int arow = wm * 64 + mi * 16 + ((lane >> 3) & 1) * 8 + (lane & 7);
                const int acol = kh * 16 + (lane >> 4) * 8;
                uint32_t Ahf[4];
                uint32_t ad = b + arow * 80 + acol * 2;
                asm volatile("ldmatrix.sync.aligned.m8n8.x4.shared.b16 {%0,%1,%2,%3},[%4];"
                             : "=r"(Ahf[0]), "=r"(Ahf[1]), "=r"(Ahf[2]), "=r"(Ahf[3]) : "r"(ad));
                #pragma unroll
                for (int ni = 0; ni < 8; ni++) MMA_F16(acc[mi][ni], Ahf, bh[ni]);
                #pragma unroll
                for (int ni = 0; ni < 8; ni++) MMA_F16(acc[mi][ni], Ahf, bl[ni]);
            }
        }
        stage++; if (stage >= P_NSTAGES) stage = 0;
    }

    const int rbase = m0 + wm * 64 + (lane >> 2);
    const int cbase = n0 + wn * 64 + (lane & 3) * 2;
    #pragma unroll
    for (int ni = 0; ni < 8; ni++) {
        int c = cbase + ni * 8;
        #pragma unroll
        for (int mi = 0; mi < 4; mi++) {
            int r = rbase + mi * 16;
            *(float2*)(C + (size_t)r * N + c) =
                make_float2(acc[mi][ni][0], acc[mi][ni][1]);
            *(float2*)(C + (size_t)(r + 8) * N + c) =
                make_float2(acc[mi][ni][2], acc[mi][ni][3]);
        }
    }
}

// ---------------------------------------------------------------------------
// Attention: fp16 hi/lo qkv planes via cp.async; 3-term QK and PV;
// single fp16 output plane (staged coalesced stores).
// ---------------------------------------------------------------------------
__global__ __launch_bounds__(128)
void attn_tc_kernel(const __half* __restrict__ qkvh,
                    const __half* __restrict__ qkvl,
                    __half* __restrict__ ao)
{
    __shared__ __half sQh[64][40], sQl[64][40];
    __shared__ __half sKh[64][40], sKl[64][40];
    __shared__ __half sVh[64][40], sVl[64][40];

    const int wx   = blockIdx.x;
    const int head = blockIdx.y;
    const int b  = wx >> 6;
    const int wi = wx & 63;
    const int wh = wi >> 3;
    const int wc = wi & 7;
    const int tid  = threadIdx.x;
    const int lane = tid & 31;
    const int warp = tid >> 5;

    {
        uint32_t dst[6] = {
            smem_u32(&sQh[0][0]), smem_u32(&sQl[0][0]),
            smem_u32(&sKh[0][0]), smem_u32(&sKl[0][0]),
            smem_u32(&sVh[0][0]), smem_u32(&sVl[0][0])
        };
        #pragma unroll
        for (int j = 0; j < 12; j++) {
            int f = j * 128 + tid;
            int m = f >> 8;
            int q = f & 255;
            int r = q >> 2;
            int c = q & 3;
            int n = ((wh * 8 + (r >> 3)) << 6) + wc * 8 + (r & 7);
            const __half* src = ((m & 1) ? qkvl : qkvh)
                + (size_t)(b * 4096 + n) * QKV_DIM + (m >> 1) * 384 + head * 32 + c * 8;
            CP_ASYNC16(dst[m] + (uint32_t)(r * 80 + c * 16), src);
        }
        CP_COMMIT();
    }
    asm volatile("cp.async.wait_group 0;" ::: "memory");
    __syncthreads();

    float cS[8][4];
    #pragma unroll
    for (int nt = 0; nt < 8; nt++)
        #pragma unroll
        for (int c = 0; c < 4; c++) cS[nt][c] = 0.0f;

    #pragma unroll
    for (int kt = 0; kt < 2; kt++) {
        const int arow = warp * 16 + ((lane >> 3) & 1) * 8 + (lane & 7);
        const int acol = kt * 16 + (lane >> 4) * 8;
        uint32_t qh[4], ql[4];
        uint32_t ad = smem_u32(&sQh[arow][acol]);
        asm volatile("ldmatrix.sync.aligned.m8n8.x4.shared.b16 {%0,%1,%2,%3},[%4];"
                     : "=r"(qh[0]), "=r"(qh[1]), "=r"(qh[2]), "=r"(qh[3]) : "r"(ad));
        ad = smem_u32(&sQl[arow][acol]);
        asm volatile("ldmatrix.sync.aligned.m8n8.x4.shared.b16 {%0,%1,%2,%3},[%4];"
                     : "=r"(ql[0]), "=r"(ql[1]), "=r"(ql[2]), "=r"(ql[3]) : "r"(ad));
        uint32_t kh2[8][2], kl2[8][2];
        #pragma unroll
        for (int nt = 0; nt < 8; nt++) {
            const int brow = nt * 8 + (lane & 7);
            const int bcol = kt * 16 + ((lane >> 3) & 1) * 8;
            uint32_t bd = smem_u32(&sKh[brow][bcol]);
            asm volatile("ldmatrix.sync.aligned.m8n8.x2.shared.b16 {%0,%1},[%2];"
                         : "=r"(kh2[nt][0]), "=r"(kh2[nt][1]) : "r"(bd));
            bd = smem_u32(&sKl[brow][bcol]);
            asm volatile("ldmatrix.sync.aligned.m8n8.x2.shared.b16 {%0,%1},[%2];"
                         : "=r"(kl2[nt][0]), "=r"(kl2[nt][1]) : "r"(bd));
        }
        #pragma unroll
        for (int nt = 0; nt < 8; nt++) MMA_F16(cS[nt], qh, kh2[nt]);
        #pragma unroll
        for (int nt = 0; nt < 8; nt++) MMA_F16(cS[nt], ql, kh2[nt]);
        #pragma unroll
        for (int nt = 0; nt < 8; nt++) MMA_F16(cS[nt], qh, kl2[nt]);
    }

    const float scale = 0.17677669529663687f;
    {
        float m0 = -1e30f, m1 = -1e30f;
        #pragma unroll
        for (int nt = 0; nt < 8; nt++) {
            m0 = fmaxf(m0, fmaxf(cS[nt][0], cS[nt][1]));
            m1 = fmaxf(m1, fmaxf(cS[nt][2], cS[nt][3]));
        }
        m0 = fmaxf(m0, __shfl_xor_sync(0xffffffffu, m0, 1));
        m0 = fmaxf(m0, __shfl_xor_sync(0xffffffffu, m0, 2));
        m1 = fmaxf(m1, __shfl_xor_sync(0xffffffffu, m1, 1));
        m1 = fmaxf(m1, __shfl_xor_sync(0xffffffffu, m1, 2));
        float s0 = 0.f, s1 = 0.f;
        #pragma unroll
        for (int nt = 0; nt < 8; nt++) {
            cS[nt][0] = __expf((cS[nt][0] - m0) * scale); s0 += cS[nt][0];
            cS[nt][1] = __expf((cS[nt][1] - m0) * scale); s0 += cS[nt][1];
            cS[nt][2] = __expf((cS[nt][2] - m1) * scale); s1 += cS[nt][2];
            cS[nt][3] = __expf((cS[nt][3] - m1) * scale); s1 += cS[nt][3];
        }
        s0 += __shfl_xor_sync(0xffffffffu, s0, 1);
        s0 += __shfl_xor_sync(0xffffffffu, s0, 2);
        s1 += __shfl_xor_sync(0xffffffffu, s1, 1);
        s1 += __shfl_xor_sync(0xffffffffu, s1, 2);
        float i0 = 1.0f / s0, i1 = 1.0f / s1;
        #pragma unroll
        for (int nt = 0; nt < 8; nt++) {
            cS[nt][0] *= i0; cS[nt][1] *= i0;
            cS[nt][2] *= i1; cS[nt][3] *= i1;
        }
    }

    uint32_t ph[4][4], pl[4][4];
    #pragma unroll
    for (int kt = 0; kt < 4; kt++) {
        #pragma unroll
        for (int half = 0; half < 2; half++) {
            int nt = 2 * kt + half;
            __half2 H0 = __floats2half2_rn(cS[nt][0], cS[nt][1]);
            __half2 H1 = __floats2half2_rn(cS[nt][2], cS[nt][3]);
            __half2 L0 = __floats2half2_rn(cS[nt][0] - __half2float(__low2half(H0)),
                                           cS[nt][1] - __half2float(__high2half(H0)));
            __half2 L1 = __floats2half2_rn(cS[nt][2] - __half2float(__low2half(H1)),
                                           cS[nt][3] - __half2float(__high2half(H1)));
            ph[kt][half * 2 + 0] = *(uint32_t*)&H0;
            ph[kt][half * 2 + 1] = *(uint32_t*)&H1;
            pl[kt][half * 2 + 0] = *(uint32_t*)&L0;
            pl[kt][half * 2 + 1] = *(uint32_t*)&L1;
        }
    }

    float cO[4][4];
    #pragma unroll
    for (int nt = 0; nt < 4; nt++)
        #pragma unroll
        for (int c = 0; c < 4; c++) cO[nt][c] = 0.0f;

    #pragma unroll
    for (int kt = 0; kt < 4; kt++) {
        const int vrow = kt * 16 + (lane & 15);
        uint32_t vh2[4][2], vl2[4][2];
        #pragma unroll
        for (int nt = 0; nt < 4; nt++) {
            uint32_t ad = smem_u32(&sVh[vrow][nt * 8]);
            asm volatile("ldmatrix.sync.aligned.m8n8.x2.trans.shared.b16 {%0,%1},[%2];"
                         : "=r"(vh2[nt][0]), "=r"(vh2[nt][1]) : "r"(ad));
            ad = smem_u32(&sVl[vrow][nt * 8]);
            asm volatile("ldmatrix.sync.aligned.m8n8.x2.trans.shared.b16 {%0,%1},[%2];"
                         : "=r"(vl2[nt][0]), "=r"(vl2[nt][1]) : "r"(ad));
        }
        #pragma unroll
        for (int nt = 0; nt < 4; nt++) MMA_F16(cO[nt], ph[kt], vh2[nt]);
        #pragma unroll
        for (int nt = 0; nt < 4; nt++) MMA_F16(cO[nt], pl[kt], vh2[nt]);
        #pragma unroll
        for (int nt = 0; nt < 4; nt++) MMA_F16(cO[nt], ph[kt], vl2[nt]);
    }

    // Staged single-plane output (reuse sQh).
    __syncthreads();
    {
        const int g0 = lane >> 2;
        const int c2 = (lane & 3) * 2;
        #pragma unroll
        for (int half = 0; half < 2; half++) {
            int r = warp * 16 + g0 + half * 8;
            #pragma unroll
            for (int nt = 0; nt < 4; nt++) {
                *(__half2*)&sQh[r][nt * 8 + c2] =
                    __floats2half2_rn(cO[nt][half * 2 + 0], cO[nt][half * 2 + 1]);
            }
        }
    }
    __syncthreads();
    {
        #pragma unroll
        for (int j = 0; j < 2; j++) {
            int f = j * 128 + tid;        // 0..255
            int r = f >> 2;               // token slot
            int ch = f & 3;               // 16B chunk of 64B row
            int n = ((wh * 8 + (r >> 3)) << 6) + wc * 8 + (r & 7);
            size_t base = (size_t)(b * 4096 + n) * C_DIM + head * 32 + ch * 8;
            *(uint4*)(ao + base) = *(const uint4*)&sQh[r][ch * 8];
        }
    }
}

// ---------------------------------------------------------------------------
// Host launcher
// ---------------------------------------------------------------------------
extern "C" void kernel_launch(void* const* d_in, const int* in_sizes, int n_in,
                              void* d_out, int out_size)
{
    const float* x      = (const float*)d_in[0];
    const float* W_qkv  = (const float*)d_in[1];
    const float* b_qkv  = (const float*)d_in[2];
    const float* W_proj = (const float*)d_in[3];
    float* out = (float*)d_out;

    __half *qkvh, *qkvl, *ao, *wqh, *wql, *wph, *wpl;
    cudaGetSymbolAddress((void**)&qkvh, g_qkvh);
    cudaGetSymbolAddress((void**)&qkvl, g_qkvl);
    cudaGetSymbolAddress((void**)&ao,   g_ao);
    cudaGetSymbolAddress((void**)&wqh,  g_wqh);
    cudaGetSymbolAddress((void**)&wql,  g_wql);
    cudaGetSymbolAddress((void**)&wph,  g_wph);
    cudaGetSymbolAddress((void**)&wpl,  g_wpl);

    cudaFuncSetAttribute(gemm_qkv_kernel,
                         cudaFuncAttributeMaxDynamicSharedMemorySize, FA_DYNSMEM);
    cudaFuncSetAttribute(gemm_proj_kernel,
                         cudaFuncAttributeMaxDynamicSharedMemorySize, PROJ_DYNSMEM);

    // Weight splits (fp16 hi/lo)
    {
        int w4 = C_DIM * QKV_DIM / 4;
        split_kernel<<<(w4 + 255) / 256, 256>>>(W_qkv, wqh, wql, w4);
        int p4 = C_DIM * C_DIM / 4;
        split_kernel<<<(p4 + 255) / 256, 256>>>(W_proj, wph, wpl, p4);
    }
    // 1) QKV projection: 2-term (weights split), qkv out as fp16 hi/lo
    {
        dim3 grid(QKV_DIM / 128, TOKENS / 128);
        gemm_qkv_kernel<<<grid, 128, FA_DYNSMEM>>>(x, wqh, wql, b_qkv,
                                                   qkvh, qkvl, QKV_DIM, C_DIM);
    }
    // 2) Windowed attention: 3-term fp16 internally, single-plane out
    {
        dim3 grid(1024, 12);
        attn_tc_kernel<<<grid, 128>>>(qkvh, qkvl, ao);
    }
    // 3) Output projection: 2-term (weights split), fp32 out
    {
        dim3 grid(C_DIM / 128, TOKENS / 128);
        gemm_proj_kernel<<<grid, 128, PROJ_DYNSMEM>>>(ao, wph, wpl, out,
                                                      C_DIM, C_DIM);
    }
}

// round 13
// speedup vs baseline: 1.3496x; 1.0003x over previous
#include <cuda_runtime.h>
#include <cuda_fp16.h>
#include <cstdint>

// x: [16,4096,384] fp32 -> out [16,4096,384] fp32
// 8x8 window attention over 64x64 grid, 12 heads, hd=32.
// Precision scheme: fp16. GEMMs 2-term (weights hi/lo split, activations
// single-rounded). Attention internally 3-term (qkv + P as hi/lo).

#define TOKENS   65536
#define C_DIM    384
#define QKV_DIM  1152

__device__ __half  g_qkvh[(size_t)TOKENS * QKV_DIM];
__device__ __half  g_qkvl[(size_t)TOKENS * QKV_DIM];
__device__ __half  g_ao  [(size_t)TOKENS * C_DIM];     // attn out, single plane
__device__ __half  g_wqh [(size_t)C_DIM * QKV_DIM];
__device__ __half  g_wql [(size_t)C_DIM * QKV_DIM];
__device__ __half  g_wph [(size_t)C_DIM * C_DIM];
__device__ __half  g_wpl [(size_t)C_DIM * C_DIM];

static __device__ __forceinline__ uint32_t smem_u32(const void* p) {
    return (uint32_t)__cvta_generic_to_shared(p);
}

#define CP_ASYNC16(smem, gptr) \
    asm volatile("cp.async.cg.shared.global [%0], [%1], 16;" :: "r"(smem), "l"(gptr))
#define CP_COMMIT() asm volatile("cp.async.commit_group;" ::: "memory")

#define MMA_F16(d, a, b)                                                       \
    asm volatile(                                                              \
        "mma.sync.aligned.m16n8k16.row.col.f32.f16.f16.f32 "                   \
        "{%0,%1,%2,%3},{%4,%5,%6,%7},{%8,%9},{%0,%1,%2,%3};"                   \
        : "+f"(d[0]), "+f"(d[1]), "+f"(d[2]), "+f"(d[3])                       \
        : "r"(a[0]), "r"(a[1]), "r"(a[2]), "r"(a[3]), "r"(b[0]), "r"(b[1]))

// ---------------------------------------------------------------------------
// fp32 -> (hi, lo) fp16 split (weights)
// ---------------------------------------------------------------------------
__global__ void split_kernel(const float* __restrict__ in,
                             __half* __restrict__ hi,
                             __half* __restrict__ lo, int n4)
{
    int i = blockIdx.x * blockDim.x + threadIdx.x;
    if (i >= n4) return;
    float4 v = ((const float4*)in)[i];
    __half h0 = __float2half_rn(v.x), h1 = __float2half_rn(v.y);
    __half h2 = __float2half_rn(v.z), h3 = __float2half_rn(v.w);
    __half2* hp = (__half2*)hi;
    __half2* lp = (__half2*)lo;
    hp[i*2]   = __halves2half2(h0, h1);
    hp[i*2+1] = __halves2half2(h2, h3);
    lp[i*2]   = __halves2half2(__float2half_rn(v.x - __half2float(h0)),
                               __float2half_rn(v.y - __half2float(h1)));
    lp[i*2+1] = __halves2half2(__float2half_rn(v.z - __half2float(h2)),
                               __float2half_rn(v.w - __half2float(h3)));
}

// ---------------------------------------------------------------------------
// Fused QKV GEMM: A fp32 -> single fp16 in-kernel; C = Ah@(Bh+Bl) + bias.
// Output: qkv as fp16 hi/lo planes (staged, coalesced stores).
// CTA 128x128, 4 warps (2x2), warp 64x64, BK=32, 2-stage cp.async.
// smem: AF32 2x18432 @0 | AH (single) 10240 @36864 | B 2x17408 @47104
// ---------------------------------------------------------------------------
#define FA_AF32   0
#define FA_AF32_ST 18432
#define FA_AH     36864
#define FA_B      47104
#define FA_B_ST   17408
#define FA_BL_OFF 8704
#define FA_DYNSMEM 81920

__global__ __launch_bounds__(128, 2)
void gemm_qkv_kernel(const float* __restrict__ A,
                     const __half* __restrict__ Bh,
                     const __half* __restrict__ Bl,
                     const float* __restrict__ bias,
                     __half* __restrict__ Ch,
                     __half* __restrict__ Cl, int N, int K)
{
    extern __shared__ char smem_raw[];
    const uint32_t sbase = smem_u32(smem_raw);

    const int tid  = threadIdx.x;
    const int lane = tid & 31;
    const int warp = tid >> 5;
    const int wm   = warp >> 1;
    const int wn   = warp & 1;
    const int m0   = blockIdx.y * 128;
    const int n0   = blockIdx.x * 128;
    const int KT   = K / 32;

    float acc[4][8][4];
    #pragma unroll
    for (int mi = 0; mi < 4; mi++)
        #pragma unroll
        for (int ni = 0; ni < 8; ni++)
            #pragma unroll
            for (int c = 0; c < 4; c++) acc[mi][ni][c] = 0.0f;

    uint32_t afo[8]; size_t afg[8];
    #pragma unroll
    for (int j = 0; j < 8; j++) {
        int idx = j * 128 + tid;
        int r = idx >> 3, c = idx & 7;
        afo[j] = (uint32_t)(r * 144 + c * 16);
        afg[j] = (size_t)r * K + c * 4;
    }
    uint32_t bso[4]; size_t bgo[4];
    #pragma unroll
    for (int j = 0; j < 4; j++) {
        int idx = j * 128 + tid;
        int br = idx >> 4, bc = idx & 15;
        bso[j] = (uint32_t)(br * 272 + bc * 16);
        bgo[j] = (size_t)br * N + bc * 8;
    }

    auto load_stage = [&](int kt, int st) {
        uint32_t ab = sbase + FA_AF32 + st * FA_AF32_ST;
        const float* pa = A + (size_t)m0 * K + kt * 32;
        #pragma unroll
        for (int j = 0; j < 8; j++) CP_ASYNC16(ab + afo[j], pa + afg[j]);
        uint32_t bb = sbase + FA_B + st * FA_B_ST;
        const __half* pbh = Bh + (size_t)(kt * 32) * N + n0;
        const __half* pbl = Bl + (size_t)(kt * 32) * N + n0;
        #pragma unroll
        for (int j = 0; j < 4; j++) CP_ASYNC16(bb + bso[j],             pbh + bgo[j]);
        #pragma unroll
        for (int j = 0; j < 4; j++) CP_ASYNC16(bb + FA_BL_OFF + bso[j], pbl + bgo[j]);
        CP_COMMIT();
    };

    load_stage(0, 0);

    for (int kt = 0; kt < KT; kt++) {
        const int st = kt & 1;
        asm volatile("cp.async.wait_group 0;" ::: "memory");
        __syncthreads();

        if (kt + 1 < KT) load_stage(kt + 1, st ^ 1);

        // Convert A fp32 -> single fp16 buffer (row = tid)
        {
            const float* arow = (const float*)(smem_raw + FA_AF32 + st * FA_AF32_ST
                                               + tid * 144);
            __half* hrow = (__half*)(smem_raw + FA_AH + tid * 80);
            #pragma unroll
            for (int j = 0; j < 8; j++) {
                float4 v = *(const float4*)(arow + j * 4);
                *(__half2*)(hrow + j * 4)     = __floats2half2_rn(v.x, v.y);
                *(__half2*)(hrow + j * 4 + 2) = __floats2half2_rn(v.z, v.w);
            }
        }
        __syncthreads();

        const uint32_t bb = sbase + FA_B + st * FA_B_ST;
        #pragma unroll
        for (int kh = 0; kh < 2; kh++) {
            uint32_t bh[8][2], bl[8][2];
            const int brow = kh * 16 + (lane & 15);
            #pragma unroll
            for (int ni = 0; ni < 8; ni++) {
                uint32_t col2 = (uint32_t)((wn * 64 + ni * 8) * 2);
                uint32_t ad = bb + brow * 272 + col2;
                asm volatile("ldmatrix.sync.aligned.m8n8.x2.trans.shared.b16 {%0,%1},[%2];"
                             : "=r"(bh[ni][0]), "=r"(bh[ni][1]) : "r"(ad));
                ad = bb + FA_BL_OFF + brow * 272 + col2;
                asm volatile("ldmatrix.sync.aligned.m8n8.x2.trans.shared.b16 {%0,%1},[%2];"
                             : "=r"(bl[ni][0]), "=r"(bl[ni][1]) : "r"(ad));
            }
            #pragma unroll
            for (int mi = 0; mi < 4; mi++) {
                const int arow = wm * 64 + mi * 16 + ((lane >> 3) & 1) * 8 + (lane & 7);
                const int acol = kh * 16 + (lane >> 4) * 8;
                uint32_t Ahf[4];
                uint32_t ad = sbase + FA_AH + arow * 80 + acol * 2;
                asm volatile("ldmatrix.sync.aligned.m8n8.x4.shared.b16 {%0,%1,%2,%3},[%4];"
                             : "=r"(Ahf[0]), "=r"(Ahf[1]), "=r"(Ahf[2]), "=r"(Ahf[3]) : "r"(ad));
                #pragma unroll
                for (int ni = 0; ni < 8; ni++) MMA_F16(acc[mi][ni], Ahf, bh[ni]);
                #pragma unroll
                for (int ni = 0; ni < 8; ni++) MMA_F16(acc[mi][ni], Ahf, bl[ni]);
            }
        }
    }

    // Staged epilogue: per plane -> smem tile -> coalesced 16B stores.
    __syncthreads();
    const int rb = wm * 64 + (lane >> 2);
    const int cb = wn * 64 + (lane & 3) * 2;
    #pragma unroll
    for (int plane = 0; plane < 2; plane++) {
        #pragma unroll
        for (int ni = 0; ni < 8; ni++) {
            int c = cb + ni * 8;
            float b0 = bias[n0 + c], b1 = bias[n0 + c + 1];
            #pragma unroll
            for (int mi = 0; mi < 4; mi++) {
                #pragma unroll
                for (int h = 0; h < 2; h++) {
                    int r = rb + mi * 16 + h * 8;
                    float v0 = acc[mi][ni][h * 2 + 0] + b0;
                    float v1 = acc[mi][ni][h * 2 + 1] + b1;
                    __half2 H = __floats2half2_rn(v0, v1);
                    __half2 val = H;
                    if (plane) {
                        val = __floats2half2_rn(v0 - __half2float(__low2half(H)),
                                                v1 - __half2float(__high2half(H)));
                    }
                    *(__half2*)(smem_raw + r * 272 + c * 2) = val;
                }
            }
        }
        __syncthreads();
        __half* Cp = plane ? Cl : Ch;
        #pragma unroll
        for (int j = 0; j < 16; j++) {
            int f = j * 128 + tid;
            int r = f >> 4, ch = f & 15;
            uint4 v = *(const uint4*)(smem_raw + r * 272 + ch * 16);
            *(uint4*)(Cp + (size_t)(m0 + r) * N + n0 + ch * 8) = v;
        }
        __syncthreads();
    }
}

// ---------------------------------------------------------------------------
// Proj GEMM: A single fp16 plane, B hi/lo, 2-term; fp32 out.
// smem per stage: A 10240 | Bh 8704 | Bl 8704 = 27648; 3 stages.
// ---------------------------------------------------------------------------
#define P_BH 10240
#define P_BL 18944
#define P_ST 27648
#define P_NSTAGES 3
#define PROJ_DYNSMEM (P_NSTAGES * P_ST)

__global__ __launch_bounds__(128, 2)
void gemm_proj_kernel(const __half* __restrict__ Ah,
                      const __half* __restrict__ Bh,
                      const __half* __restrict__ Bl,
                      float* __restrict__ C, int N, int K)
{
    extern __shared__ char smem_raw[];
    const uint32_t sbase = smem_u32(smem_raw);

    const int tid  = threadIdx.x;
    const int lane = tid & 31;
    const int warp = tid >> 5;
    const int wm   = warp >> 1;
    const int wn   = warp & 1;
    const int m0   = blockIdx.y * 128;
    const int n0   = blockIdx.x * 128;
    const int KT   = K / 32;

    float acc[4][8][4];
    #pragma unroll
    for (int mi = 0; mi < 4; mi++)
        #pragma unroll
        for (int ni = 0; ni < 8; ni++)
            #pragma unroll
            for (int c = 0; c < 4; c++) acc[mi][ni][c] = 0.0f;

    uint32_t aso[4]; size_t ago[4];
    uint32_t bso[4]; size_t bgo[4];
    #pragma unroll
    for (int j = 0; j < 4; j++) {
        int idx = j * 128 + tid;
        int ar = idx >> 2, ac = idx & 3;
        aso[j] = (uint32_t)(ar * 80 + ac * 16);
        ago[j] = (size_t)ar * K + ac * 8;
        int br = idx >> 4, bc = idx & 15;
        bso[j] = (uint32_t)(br * 272 + bc * 16);
        bgo[j] = (size_t)br * N + bc * 8;
    }

    auto load_stage = [&](int kt, int st) {
        uint32_t b = sbase + st * P_ST;
        const __half* pa  = Ah + (size_t)m0 * K + kt * 32;
        const __half* pbh = Bh + (size_t)(kt * 32) * N + n0;
        const __half* pbl = Bl + (size_t)(kt * 32) * N + n0;
        #pragma unroll
        for (int j = 0; j < 4; j++) CP_ASYNC16(b + aso[j],        pa  + ago[j]);
        #pragma unroll
        for (int j = 0; j < 4; j++) CP_ASYNC16(b + P_BH + bso[j], pbh + bgo[j]);
        #pragma unroll
        for (int j = 0; j < 4; j++) CP_ASYNC16(b + P_BL + bso[j], pbl + bgo[j]);
        CP_COMMIT();
    };

    load_stage(0, 0);
    load_stage(1, 1);

    int stage = 0;
    for (int kt = 0; kt < KT; kt++) {
        if (kt + 1 < KT) {
            asm volatile("cp.async.wait_group 1;" ::: "memory");
        } else {
            asm volatile("cp.async.wait_group 0;" ::: "memory");
        }
        __syncthreads();

        if (kt + 2 < KT) {
            int st2 = stage + 2; if (st2 >= P_NSTAGES) st2 -= P_NSTAGES;
            load_stage(kt + 2, st2);
        }

        const uint32_t b = sbase + stage * P_ST;
        #pragma unroll
        for (int kh = 0; kh < 2; kh++) {
            uint32_t bh[8][2], bl[8][2];
            const int brow = kh * 16 + (lane & 15);
            #pragma unroll
            for (int ni = 0; ni < 8; ni++) {
                uint32_t col2 = (uint32_t)((wn * 64 + ni * 8) * 2);
                uint32_t ad = b + P_BH + brow * 272 + col2;
                asm volatile("ldmatrix.sync.aligned.m8n8.x2.trans.shared.b16 {%0,%1},[%2];"
                             : "=r"(bh[ni][0]), "=r"(bh[ni][1]) : "r"(ad));
                ad = b + P_BL + brow * 272 + col2;
                asm volatile("ldmatrix.sync.aligned.m8n8.x2.trans.shared.b16 {%0,%1},[%2];"
                             : "=r"(bl[ni][0]), "=r"(bl[ni][1]) : "r"(ad));
            }
            #pragma unroll
            for (int mi = 0; mi < 4; mi++) {
                const int arow = wm * 64 + mi * 16 + ((lane >> 3) & 1) * 8 + (lane & 7);
                const int acol = kh * 16 + (lane >> 4) * 8;
                uint32_t Ahf[4];
                uint32_t ad = b + arow * 80 + acol * 2;
                asm volatile("ldmatrix.sync.aligned.m8n8.x4.shared.b16 {%0,%1,%2,%3},[%4];"
                             : "=r"(Ahf[0]), "=r"(Ahf[1]), "=r"(Ahf[2]), "=r"(Ahf[3]) : "r"(ad));
                #pragma unroll
                for (int ni = 0; ni < 8; ni++) MMA_F16(acc[mi][ni], Ahf, bh[ni]);
                #pragma unroll
                for (int ni = 0; ni < 8; ni++) MMA_F16(acc[mi][ni], Ahf, bl[ni]);
            }
        }
        stage++; if (stage >= P_NSTAGES) stage = 0;
    }

    const int rbase = m0 + wm * 64 + (lane >> 2);
    const int cbase = n0 + wn * 64 + (lane & 3) * 2;
    #pragma unroll
    for (int ni = 0; ni < 8; ni++) {
        int c = cbase + ni * 8;
        #pragma unroll
        for (int mi = 0; mi < 4; mi++) {
            int r = rbase + mi * 16;
            *(float2*)(C + (size_t)r * N + c) =
                make_float2(acc[mi][ni][0], acc[mi][ni][1]);
            *(float2*)(C + (size_t)(r + 8) * N + c) =
                make_float2(acc[mi][ni][2], acc[mi][ni][3]);
        }
    }
}

// ---------------------------------------------------------------------------
// Attention: fp16 hi/lo qkv planes via cp.async; 3-term QK and PV;
// single fp16 output plane (staged coalesced stores).
// ---------------------------------------------------------------------------
__global__ __launch_bounds__(128)
void attn_tc_kernel(const __half* __restrict__ qkvh,
                    const __half* __restrict__ qkvl,
                    __half* __restrict__ ao)
{
    __shared__ __half sQh[64][40], sQl[64][40];
    __shared__ __half sKh[64][40], sKl[64][40];
    __shared__ __half sVh[64][40], sVl[64][40];

    const int wx   = blockIdx.x;
    const int head = blockIdx.y;
    const int b  = wx >> 6;
    const int wi = wx & 63;
    const int wh = wi >> 3;
    const int wc = wi & 7;
    const int tid  = threadIdx.x;
    const int lane = tid & 31;
    const int warp = tid >> 5;

    {
        uint32_t dst[6] = {
            smem_u32(&sQh[0][0]), smem_u32(&sQl[0][0]),
            smem_u32(&sKh[0][0]), smem_u32(&sKl[0][0]),
            smem_u32(&sVh[0][0]), smem_u32(&sVl[0][0])
        };
        #pragma unroll
        for (int j = 0; j < 12; j++) {
            int f = j * 128 + tid;
            int m = f >> 8;
            int q = f & 255;
            int r = q >> 2;
            int c = q & 3;
            int n = ((wh * 8 + (r >> 3)) << 6) + wc * 8 + (r & 7);
            const __half* src = ((m & 1) ? qkvl : qkvh)
                + (size_t)(b * 4096 + n) * QKV_DIM + (m >> 1) * 384 + head * 32 + c * 8;
            CP_ASYNC16(dst[m] + (uint32_t)(r * 80 + c * 16), src);
        }
        CP_COMMIT();
    }
    asm volatile("cp.async.wait_group 0;" ::: "memory");
    __syncthreads();

    float cS[8][4];
    #pragma unroll
    for (int nt = 0; nt < 8; nt++)
        #pragma unroll
        for (int c = 0; c < 4; c++) cS[nt][c] = 0.0f;

    #pragma unroll
    for (int kt = 0; kt < 2; kt++) {
        const int arow = warp * 16 + ((lane >> 3) & 1) * 8 + (lane & 7);
        const int acol = kt * 16 + (lane >> 4) * 8;
        uint32_t qh[4], ql[4];
        uint32_t ad = smem_u32(&sQh[arow][acol]);
        asm volatile("ldmatrix.sync.aligned.m8n8.x4.shared.b16 {%0,%1,%2,%3},[%4];"
                     : "=r"(qh[0]), "=r"(qh[1]), "=r"(qh[2]), "=r"(qh[3]) : "r"(ad));
        ad = smem_u32(&sQl[arow][acol]);
        asm volatile("ldmatrix.sync.aligned.m8n8.x4.shared.b16 {%0,%1,%2,%3},[%4];"
                     : "=r"(ql[0]), "=r"(ql[1]), "=r"(ql[2]), "=r"(ql[3]) : "r"(ad));
        uint32_t kh2[8][2], kl2[8][2];
        #pragma unroll
        for (int nt = 0; nt < 8; nt++) {
            const int brow = nt * 8 + (lane & 7);
            const int bcol = kt * 16 + ((lane >> 3) & 1) * 8;
            uint32_t bd = smem_u32(&sKh[brow][bcol]);
            asm volatile("ldmatrix.sync.aligned.m8n8.x2.shared.b16 {%0,%1},[%2];"
                         : "=r"(kh2[nt][0]), "=r"(kh2[nt][1]) : "r"(bd));
            bd = smem_u32(&sKl[brow][bcol]);
            asm volatile("ldmatrix.sync.aligned.m8n8.x2.shared.b16 {%0,%1},[%2];"
                         : "=r"(kl2[nt][0]), "=r"(kl2[nt][1]) : "r"(bd));
        }
        #pragma unroll
        for (int nt = 0; nt < 8; nt++) MMA_F16(cS[nt], qh, kh2[nt]);
        #pragma unroll
        for (int nt = 0; nt < 8; nt++) MMA_F16(cS[nt], ql, kh2[nt]);
        #pragma unroll
        for (int nt = 0; nt < 8; nt++) MMA_F16(cS[nt], qh, kl2[nt]);
    }

    const float scale = 0.17677669529663687f;
    {
        float m0 = -1e30f, m1 = -1e30f;
        #pragma unroll
        for (int nt = 0; nt < 8; nt++) {
            m0 = fmaxf(m0, fmaxf(cS[nt][0], cS[nt][1]));
            m1 = fmaxf(m1, fmaxf(cS[nt][2], cS[nt][3]));
        }
        m0 = fmaxf(m0, __shfl_xor_sync(0xffffffffu, m0, 1));
        m0 = fmaxf(m0, __shfl_xor_sync(0xffffffffu, m0, 2));
        m1 = fmaxf(m1, __shfl_xor_sync(0xffffffffu, m1, 1));
        m1 = fmaxf(m1, __shfl_xor_sync(0xffffffffu, m1, 2));
        float s0 = 0.f, s1 = 0.f;
        #pragma unroll
        for (int nt = 0; nt < 8; nt++) {
            cS[nt][0] = __expf((cS[nt][0] - m0) * scale); s0 += cS[nt][0];
            cS[nt][1] = __expf((cS[nt][1] - m0) * scale); s0 += cS[nt][1];
            cS[nt][2] = __expf((cS[nt][2] - m1) * scale); s1 += cS[nt][2];
            cS[nt][3] = __expf((cS[nt][3] - m1) * scale); s1 += cS[nt][3];
        }
        s0 += __shfl_xor_sync(0xffffffffu, s0, 1);
        s0 += __shfl_xor_sync(0xffffffffu, s0, 2);
        s1 += __shfl_xor_sync(0xffffffffu, s1, 1);
        s1 += __shfl_xor_sync(0xffffffffu, s1, 2);
        float i0 = 1.0f / s0, i1 = 1.0f / s1;
        #pragma unroll
        for (int nt = 0; nt < 8; nt++) {
            cS[nt][0] *= i0; cS[nt][1] *= i0;
            cS[nt][2] *= i1; cS[nt][3] *= i1;
        }
    }

    uint32_t ph[4][4], pl[4][4];
    #pragma unroll
    for (int kt = 0; kt < 4; kt++) {
        #pragma unroll
        for (int half = 0; half < 2; half++) {
            int nt = 2 * kt + half;
            __half2 H0 = __floats2half2_rn(cS[nt][0], cS[nt][1]);
            __half2 H1 = __floats2half2_rn(cS[nt][2], cS[nt][3]);
            __half2 L0 = __floats2half2_rn(cS[nt][0] - __half2float(__low2half(H0)),
                                           cS[nt][1] - __half2float(__high2half(H0)));
            __half2 L1 = __floats2half2_rn(cS[nt][2] - __half2float(__low2half(H1)),
                                           cS[nt][3] - __half2float(__high2half(H1)));
            ph[kt][half * 2 + 0] = *(uint32_t*)&H0;
            ph[kt][half * 2 + 1] = *(uint32_t*)&H1;
            pl[kt][half * 2 + 0] = *(uint32_t*)&L0;
            pl[kt][half * 2 + 1] = *(uint32_t*)&L1;
        }
    }

    float cO[4][4];
    #pragma unroll
    for (int nt = 0; nt < 4; nt++)
        #pragma unroll
        for (int c = 0; c < 4; c++) cO[nt][c] = 0.0f;

    #pragma unroll
    for (int kt = 0; kt < 4; kt++) {
        const int vrow = kt * 16 + (lane & 15);
        uint32_t vh2[4][2], vl2[4][2];
        #pragma unroll
        for (int nt = 0; nt < 4; nt++) {
            uint32_t ad = smem_u32(&sVh[vrow][nt * 8]);
            asm volatile("ldmatrix.sync.aligned.m8n8.x2.trans.shared.b16 {%0,%1},[%2];"
                         : "=r"(vh2[nt][0]), "=r"(vh2[nt][1]) : "r"(ad));
            ad = smem_u32(&sVl[vrow][nt * 8]);
            asm volatile("ldmatrix.sync.aligned.m8n8.x2.trans.shared.b16 {%0,%1},[%2];"
                         : "=r"(vl2[nt][0]), "=r"(vl2[nt][1]) : "r"(ad));
        }
        #pragma unroll
        for (int nt = 0; nt < 4; nt++) MMA_F16(cO[nt], ph[kt], vh2[nt]);
        #pragma unroll
        for (int nt = 0; nt < 4; nt++) MMA_F16(cO[nt], pl[kt], vh2[nt]);
        #pragma unroll
        for (int nt = 0; nt < 4; nt++) MMA_F16(cO[nt], ph[kt], vl2[nt]);
    }

    // Staged single-plane output (reuse sQh).
    __syncthreads();
    {
        const int g0 = lane >> 2;
        const int c2 = (lane & 3) * 2;
        #pragma unroll
        for (int half = 0; half < 2; half++) {
            int r = warp * 16 + g0 + half * 8;
            #pragma unroll
            for (int nt = 0; nt < 4; nt++) {
                *(__half2*)&sQh[r][nt * 8 + c2] =
                    __floats2half2_rn(cO[nt][half * 2 + 0], cO[nt][half * 2 + 1]);
            }
        }
    }
    __syncthreads();
    {
        #pragma unroll
        for (int j = 0; j < 2; j++) {
            int f = j * 128 + tid;        // 0..255
            int r = f >> 2;               // token slot
            int ch = f & 3;               // 16B chunk of 64B row
            int n = ((wh * 8 + (r >> 3)) << 6) + wc * 8 + (r & 7);
            size_t base = (size_t)(b * 4096 + n) * C_DIM + head * 32 + ch * 8;
            *(uint4*)(ao + base) = *(const uint4*)&sQh[r][ch * 8];
        }
    }
}

// ---------------------------------------------------------------------------
// Host launcher
// ---------------------------------------------------------------------------
extern "C" void kernel_launch(void* const* d_in, const int* in_sizes, int n_in,
                              void* d_out, int out_size)
{
    const float* x      = (const float*)d_in[0];
    const float* W_qkv  = (const float*)d_in[1];
    const float* b_qkv  = (const float*)d_in[2];
    const float* W_proj = (const float*)d_in[3];
    float* out = (float*)d_out;

    __half *qkvh, *qkvl, *ao, *wqh, *wql, *wph, *wpl;
    cudaGetSymbolAddress((void**)&qkvh, g_qkvh);
    cudaGetSymbolAddress((void**)&qkvl, g_qkvl);
    cudaGetSymbolAddress((void**)&ao,   g_ao);
    cudaGetSymbolAddress((void**)&wqh,  g_wqh);
    cudaGetSymbolAddress((void**)&wql,  g_wql);
    cudaGetSymbolAddress((void**)&wph,  g_wph);
    cudaGetSymbolAddress((void**)&wpl,  g_wpl);

    cudaFuncSetAttribute(gemm_qkv_kernel,
                         cudaFuncAttributeMaxDynamicSharedMemorySize, FA_DYNSMEM);
    cudaFuncSetAttribute(gemm_proj_kernel,
                         cudaFuncAttributeMaxDynamicSharedMemorySize, PROJ_DYNSMEM);

    // Weight splits (fp16 hi/lo)
    {
        int w4 = C_DIM * QKV_DIM / 4;
        split_kernel<<<(w4 + 255) / 256, 256>>>(W_qkv, wqh, wql, w4);
        int p4 = C_DIM * C_DIM / 4;
        split_kernel<<<(p4 + 255) / 256, 256>>>(W_proj, wph, wpl, p4);
    }
    // 1) QKV projection: 2-term (weights split), qkv out as fp16 hi/lo
    {
        dim3 grid(QKV_DIM / 128, TOKENS / 128);
        gemm_qkv_kernel<<<grid, 128, FA_DYNSMEM>>>(x, wqh, wql, b_qkv,
                                                   qkvh, qkvl, QKV_DIM, C_DIM);
    }
    // 2) Windowed attention: 3-term fp16 internally, single-plane out
    {
        dim3 grid(1024, 12);
        attn_tc_kernel<<<grid, 128>>>(qkvh, qkvl, ao);
    }
    // 3) Output projection: 2-term (weights split), fp32 out
    {
        dim3 grid(C_DIM / 128, TOKENS / 128);
        gemm_proj_kernel<<<grid, 128, PROJ_DYNSMEM>>>(ao, wph, wpl, out,
                                                      C_DIM, C_DIM);
    }
}

// round 14
// speedup vs baseline: 1.7612x; 1.3050x over previous
#include <cuda_runtime.h>
#include <cuda_fp16.h>
#include <cstdint>

// x: [16,4096,384] fp32 -> out [16,4096,384] fp32
// 8x8 window attention over 64x64 grid, 12 heads, hd=32.
// Precision: fp16 1-term GEMMs (weights + activations single-rounded);
// attention internally 3-term (qkv hi/lo planes, P hi/lo).

#define TOKENS   65536
#define C_DIM    384
#define QKV_DIM  1152

__device__ __half  g_qkvh[(size_t)TOKENS * QKV_DIM];
__device__ __half  g_qkvl[(size_t)TOKENS * QKV_DIM];
__device__ __half  g_ao  [(size_t)TOKENS * C_DIM];
__device__ __half  g_wq  [(size_t)C_DIM * QKV_DIM];
__device__ __half  g_wp  [(size_t)C_DIM * C_DIM];

static __device__ __forceinline__ uint32_t smem_u32(const void* p) {
    return (uint32_t)__cvta_generic_to_shared(p);
}

#define CP_ASYNC16(smem, gptr) \
    asm volatile("cp.async.cg.shared.global [%0], [%1], 16;" :: "r"(smem), "l"(gptr))
#define CP_COMMIT() asm volatile("cp.async.commit_group;" ::: "memory")

#define MMA_F16(d, a, b)                                                       \
    asm volatile(                                                              \
        "mma.sync.aligned.m16n8k16.row.col.f32.f16.f16.f32 "                   \
        "{%0,%1,%2,%3},{%4,%5,%6,%7},{%8,%9},{%0,%1,%2,%3};"                   \
        : "+f"(d[0]), "+f"(d[1]), "+f"(d[2]), "+f"(d[3])                       \
        : "r"(a[0]), "r"(a[1]), "r"(a[2]), "r"(a[3]), "r"(b[0]), "r"(b[1]))

// ---------------------------------------------------------------------------
// fp32 -> fp16 convert (weights, single plane)
// ---------------------------------------------------------------------------
__global__ void convert_kernel(const float* __restrict__ in,
                               __half* __restrict__ out16, int n4)
{
    int i = blockIdx.x * blockDim.x + threadIdx.x;
    if (i >= n4) return;
    float4 v = ((const float4*)in)[i];
    __half2* op = (__half2*)out16;
    op[i*2]   = __floats2half2_rn(v.x, v.y);
    op[i*2+1] = __floats2half2_rn(v.z, v.w);
}

// ---------------------------------------------------------------------------
// QKV GEMM (1-term): A fp32 -> fp16 in-kernel; C = A16 @ W16 + bias.
// Output qkv as fp16 hi/lo planes (staged coalesced stores — attention
// consumes hi/lo for its 3-term path).
// smem: AF32 2x18432 @0 | AH 10240 @36864 | B 2x8704 @47104  (=64512)
// ---------------------------------------------------------------------------
#define FA_AF32    0
#define FA_AF32_ST 18432
#define FA_AH      36864
#define FA_B       47104
#define FA_B_ST    8704
#define FA_DYNSMEM 64512

__global__ __launch_bounds__(128, 2)
void gemm_qkv_kernel(const float* __restrict__ A,
                     const __half* __restrict__ B16,
                     const float* __restrict__ bias,
                     __half* __restrict__ Ch,
                     __half* __restrict__ Cl, int N, int K)
{
    extern __shared__ char smem_raw[];
    const uint32_t sbase = smem_u32(smem_raw);

    const int tid  = threadIdx.x;
    const int lane = tid & 31;
    const int warp = tid >> 5;
    const int wm   = warp >> 1;
    const int wn   = warp & 1;
    const int m0   = blockIdx.y * 128;
    const int n0   = blockIdx.x * 128;
    const int KT   = K / 32;

    float acc[4][8][4];
    #pragma unroll
    for (int mi = 0; mi < 4; mi++)
        #pragma unroll
        for (int ni = 0; ni < 8; ni++)
            #pragma unroll
            for (int c = 0; c < 4; c++) acc[mi][ni][c] = 0.0f;

    uint32_t afo[8]; size_t afg[8];
    #pragma unroll
    for (int j = 0; j < 8; j++) {
        int idx = j * 128 + tid;
        int r = idx >> 3, c = idx & 7;
        afo[j] = (uint32_t)(r * 144 + c * 16);
        afg[j] = (size_t)r * K + c * 4;
    }
    uint32_t bso[4]; size_t bgo[4];
    #pragma unroll
    for (int j = 0; j < 4; j++) {
        int idx = j * 128 + tid;
        int br = idx >> 4, bc = idx & 15;
        bso[j] = (uint32_t)(br * 272 + bc * 16);
        bgo[j] = (size_t)br * N + bc * 8;
    }

    auto load_stage = [&](int kt, int st) {
        uint32_t ab = sbase + FA_AF32 + st * FA_AF32_ST;
        const float* pa = A + (size_t)m0 * K + kt * 32;
        #pragma unroll
        for (int j = 0; j < 8; j++) CP_ASYNC16(ab + afo[j], pa + afg[j]);
        uint32_t bb = sbase + FA_B + st * FA_B_ST;
        const __half* pb = B16 + (size_t)(kt * 32) * N + n0;
        #pragma unroll
        for (int j = 0; j < 4; j++) CP_ASYNC16(bb + bso[j], pb + bgo[j]);
        CP_COMMIT();
    };

    load_stage(0, 0);

    for (int kt = 0; kt < KT; kt++) {
        const int st = kt & 1;
        asm volatile("cp.async.wait_group 0;" ::: "memory");
        __syncthreads();

        if (kt + 1 < KT) load_stage(kt + 1, st ^ 1);

        // Convert A fp32 -> fp16 (row = tid)
        {
            const float* arow = (const float*)(smem_raw + FA_AF32 + st * FA_AF32_ST
                                               + tid * 144);
            __half* hrow = (__half*)(smem_raw + FA_AH + tid * 80);
            #pragma unroll
            for (int j = 0; j < 8; j++) {
                float4 v = *(const float4*)(arow + j * 4);
                *(__half2*)(hrow + j * 4)     = __floats2half2_rn(v.x, v.y);
                *(__half2*)(hrow + j * 4 + 2) = __floats2half2_rn(v.z, v.w);
            }
        }
        __syncthreads();

        const uint32_t bb = sbase + FA_B + st * FA_B_ST;
        #pragma unroll
        for (int kh = 0; kh < 2; kh++) {
            uint32_t bf[8][2];
            const int brow = kh * 16 + (lane & 15);
            #pragma unroll
            for (int ni = 0; ni < 8; ni++) {
                uint32_t ad = bb + brow * 272 + (uint32_t)((wn * 64 + ni * 8) * 2);
                asm volatile("ldmatrix.sync.aligned.m8n8.x2.trans.shared.b16 {%0,%1},[%2];"
                             : "=r"(bf[ni][0]), "=r"(bf[ni][1]) : "r"(ad));
            }
            #pragma unroll
            for (int mi = 0; mi < 4; mi++) {
                const int arow = wm * 64 + mi * 16 + ((lane >> 3) & 1) * 8 + (lane & 7);
                const int acol = kh * 16 + (lane >> 4) * 8;
                uint32_t Af[4];
                uint32_t ad = sbase + FA_AH + arow * 80 + acol * 2;
                asm volatile("ldmatrix.sync.aligned.m8n8.x4.shared.b16 {%0,%1,%2,%3},[%4];"
                             : "=r"(Af[0]), "=r"(Af[1]), "=r"(Af[2]), "=r"(Af[3]) : "r"(ad));
                #pragma unroll
                for (int ni = 0; ni < 8; ni++) MMA_F16(acc[mi][ni], Af, bf[ni]);
            }
        }
    }

    // Staged epilogue: per plane -> smem tile -> coalesced 16B stores.
    __syncthreads();
    const int rb = wm * 64 + (lane >> 2);
    const int cb = wn * 64 + (lane & 3) * 2;
    #pragma unroll
    for (int plane = 0; plane < 2; plane++) {
        #pragma unroll
        for (int ni = 0; ni < 8; ni++) {
            int c = cb + ni * 8;
            float b0 = bias[n0 + c], b1 = bias[n0 + c + 1];
            #pragma unroll
            for (int mi = 0; mi < 4; mi++) {
                #pragma unroll
                for (int h = 0; h < 2; h++) {
                    int r = rb + mi * 16 + h * 8;
                    float v0 = acc[mi][ni][h * 2 + 0] + b0;
                    float v1 = acc[mi][ni][h * 2 + 1] + b1;
                    __half2 H = __floats2half2_rn(v0, v1);
                    __half2 val = H;
                    if (plane) {
                        val = __floats2half2_rn(v0 - __half2float(__low2half(H)),
                                                v1 - __half2float(__high2half(H)));
                    }
                    *(__half2*)(smem_raw + r * 272 + c * 2) = val;
                }
            }
        }
        __syncthreads();
        __half* Cp = plane ? Cl : Ch;
        #pragma unroll
        for (int j = 0; j < 16; j++) {
            int f = j * 128 + tid;
            int r = f >> 4, ch = f & 15;
            uint4 v = *(const uint4*)(smem_raw + r * 272 + ch * 16);
            *(uint4*)(Cp + (size_t)(m0 + r) * N + n0 + ch * 8) = v;
        }
        __syncthreads();
    }
}

// ---------------------------------------------------------------------------
// Proj GEMM (1-term): A fp16 plane @ W fp16; fp32 out.
// smem per stage: A 10240 | B 8704 = 18944; 3 stages (=56832).
// ---------------------------------------------------------------------------
#define P_B  10240
#define P_ST 18944
#define P_NSTAGES 3
#define PROJ_DYNSMEM (P_NSTAGES * P_ST)

__global__ __launch_bounds__(128, 2)
void gemm_proj_kernel(const __half* __restrict__ A16,
                      const __half* __restrict__ B16,
                      float* __restrict__ C, int N, int K)
{
    extern __shared__ char smem_raw[];
    const uint32_t sbase = smem_u32(smem_raw);

    const int tid  = threadIdx.x;
    const int lane = tid & 31;
    const int warp = tid >> 5;
    const int wm   = warp >> 1;
    const int wn   = warp & 1;
    const int m0   = blockIdx.y * 128;
    const int n0   = blockIdx.x * 128;
    const int KT   = K / 32;

    float acc[4][8][4];
    #pragma unroll
    for (int mi = 0; mi < 4; mi++)
        #pragma unroll
        for (int ni = 0; ni < 8; ni++)
            #pragma unroll
            for (int c = 0; c < 4; c++) acc[mi][ni][c] = 0.0f;

    uint32_t aso[4]; size_t ago[4];
    uint32_t bso[4]; size_t bgo[4];
    #pragma unroll
    for (int j = 0; j < 4; j++) {
        int idx = j * 128 + tid;
        int ar = idx >> 2, ac = idx & 3;
        aso[j] = (uint32_t)(ar * 80 + ac * 16);
        ago[j] = (size_t)ar * K + ac * 8;
        int br = idx >> 4, bc = idx & 15;
        bso[j] = (uint32_t)(br * 272 + bc * 16);
        bgo[j] = (size_t)br * N + bc * 8;
    }

    auto load_stage = [&](int kt, int st) {
        uint32_t b = sbase + st * P_ST;
        const __half* pa = A16 + (size_t)m0 * K + kt * 32;
        const __half* pb = B16 + (size_t)(kt * 32) * N + n0;
        #pragma unroll
        for (int j = 0; j < 4; j++) CP_ASYNC16(b + aso[j],       pa + ago[j]);
        #pragma unroll
        for (int j = 0; j < 4; j++) CP_ASYNC16(b + P_B + bso[j], pb + bgo[j]);
        CP_COMMIT();
    };

    load_stage(0, 0);
    load_stage(1, 1);

    int stage = 0;
    for (int kt = 0; kt < KT; kt++) {
        if (kt + 1 < KT) {
            asm volatile("cp.async.wait_group 1;" ::: "memory");
        } else {
            asm volatile("cp.async.wait_group 0;" ::: "memory");
        }
        __syncthreads();

        if (kt + 2 < KT) {
            int st2 = stage + 2; if (st2 >= P_NSTAGES) st2 -= P_NSTAGES;
            load_stage(kt + 2, st2);
        }

        const uint32_t b = sbase + stage * P_ST;
        #pragma unroll
        for (int kh = 0; kh < 2; kh++) {
            uint32_t bf[8][2];
            const int brow = kh * 16 + (lane & 15);
            #pragma unroll
            for (int ni = 0; ni < 8; ni++) {
                uint32_t ad = b + P_B + brow * 272 + (uint32_t)((wn * 64 + ni * 8) * 2);
                asm volatile("ldmatrix.sync.aligned.m8n8.x2.trans.shared.b16 {%0,%1},[%2];"
                             : "=r"(bf[ni][0]), "=r"(bf[ni][1]) : "r"(ad));
            }
            #pragma unroll
            for (int mi = 0; mi < 4; mi++) {
                const int arow = wm * 64 + mi * 16 + ((lane >> 3) & 1) * 8 + (lane & 7);
                const int acol = kh * 16 + (lane >> 4) * 8;
                uint32_t Af[4];
                uint32_t ad = b + arow * 80 + acol * 2;
                asm volatile("ldmatrix.sync.aligned.m8n8.x4.shared.b16 {%0,%1,%2,%3},[%4];"
                             : "=r"(Af[0]), "=r"(Af[1]), "=r"(Af[2]), "=r"(Af[3]) : "r"(ad));
                #pragma unroll
                for (int ni = 0; ni < 8; ni++) MMA_F16(acc[mi][ni], Af, bf[ni]);
            }
        }
        stage++; if (stage >= P_NSTAGES) stage = 0;
    }

    const int rbase = m0 + wm * 64 + (lane >> 2);
    const int cbase = n0 + wn * 64 + (lane & 3) * 2;
    #pragma unroll
    for (int ni = 0; ni < 8; ni++) {
        int c = cbase + ni * 8;
        #pragma unroll
        for (int mi = 0; mi < 4; mi++) {
            int r = rbase + mi * 16;
            *(float2*)(C + (size_t)r * N + c) =
                make_float2(acc[mi][ni][0], acc[mi][ni][1]);
            *(float2*)(C + (size_t)(r + 8) * N + c) =
                make_float2(acc[mi][ni][2], acc[mi][ni][3]);
        }
    }
}

// ---------------------------------------------------------------------------
// Attention: fp16 hi/lo qkv planes via cp.async; 3-term QK and PV;
// single fp16 output plane (staged coalesced stores). Unchanged from R13.
// ---------------------------------------------------------------------------
__global__ __launch_bounds__(128)
void attn_tc_kernel(const __half* __restrict__ qkvh,
                    const __half* __restrict__ qkvl,
                    __half* __restrict__ ao)
{
    __shared__ __half sQh[64][40], sQl[64][40];
    __shared__ __half sKh[64][40], sKl[64][40];
    __shared__ __half sVh[64][40], sVl[64][40];

    const int wx   = blockIdx.x;
    const int head = blockIdx.y;
    const int b  = wx >> 6;
    const int wi = wx & 63;
    const int wh = wi >> 3;
    const int wc = wi & 7;
    const int tid  = threadIdx.x;
    const int lane = tid & 31;
    const int warp = tid >> 5;

    {
        uint32_t dst[6] = {
            smem_u32(&sQh[0][0]), smem_u32(&sQl[0][0]),
            smem_u32(&sKh[0][0]), smem_u32(&sKl[0][0]),
            smem_u32(&sVh[0][0]), smem_u32(&sVl[0][0])
        };
        #pragma unroll
        for (int j = 0; j < 12; j++) {
            int f = j * 128 + tid;
            int m = f >> 8;
            int q = f & 255;
            int r = q >> 2;
            int c = q & 3;
            int n = ((wh * 8 + (r >> 3)) << 6) + wc * 8 + (r & 7);
            const __half* src = ((m & 1) ? qkvl : qkvh)
                + (size_t)(b * 4096 + n) * QKV_DIM + (m >> 1) * 384 + head * 32 + c * 8;
            CP_ASYNC16(dst[m] + (uint32_t)(r * 80 + c * 16), src);
        }
        CP_COMMIT();
    }
    asm volatile("cp.async.wait_group 0;" ::: "memory");
    __syncthreads();

    float cS[8][4];
    #pragma unroll
    for (int nt = 0; nt < 8; nt++)
        #pragma unroll
        for (int c = 0; c < 4; c++) cS[nt][c] = 0.0f;

    #pragma unroll
    for (int kt = 0; kt < 2; kt++) {
        const int arow = warp * 16 + ((lane >> 3) & 1) * 8 + (lane & 7);
        const int acol = kt * 16 + (lane >> 4) * 8;
        uint32_t qh[4], ql[4];
        uint32_t ad = smem_u32(&sQh[arow][acol]);
        asm volatile("ldmatrix.sync.aligned.m8n8.x4.shared.b16 {%0,%1,%2,%3},[%4];"
                     : "=r"(qh[0]), "=r"(qh[1]), "=r"(qh[2]), "=r"(qh[3]) : "r"(ad));
        ad = smem_u32(&sQl[arow][acol]);
        asm volatile("ldmatrix.sync.aligned.m8n8.x4.shared.b16 {%0,%1,%2,%3},[%4];"
                     : "=r"(ql[0]), "=r"(ql[1]), "=r"(ql[2]), "=r"(ql[3]) : "r"(ad));
        uint32_t kh2[8][2], kl2[8][2];
        #pragma unroll
        for (int nt = 0; nt < 8; nt++) {
            const int brow = nt * 8 + (lane & 7);
            const int bcol = kt * 16 + ((lane >> 3) & 1) * 8;
            uint32_t bd = smem_u32(&sKh[brow][bcol]);
            asm volatile("ldmatrix.sync.aligned.m8n8.x2.shared.b16 {%0,%1},[%2];"
                         : "=r"(kh2[nt][0]), "=r"(kh2[nt][1]) : "r"(bd));
            bd = smem_u32(&sKl[brow][bcol]);
            asm volatile("ldmatrix.sync.aligned.m8n8.x2.shared.b16 {%0,%1},[%2];"
                         : "=r"(kl2[nt][0]), "=r"(kl2[nt][1]) : "r"(bd));
        }
        #pragma unroll
        for (int nt = 0; nt < 8; nt++) MMA_F16(cS[nt], qh, kh2[nt]);
        #pragma unroll
        for (int nt = 0; nt < 8; nt++) MMA_F16(cS[nt], ql, kh2[nt]);
        #pragma unroll
        for (int nt = 0; nt < 8; nt++) MMA_F16(cS[nt], qh, kl2[nt]);
    }

    const float scale = 0.17677669529663687f;
    {
        float m0 = -1e30f, m1 = -1e30f;
        #pragma unroll
        for (int nt = 0; nt < 8; nt++) {
            m0 = fmaxf(m0, fmaxf(cS[nt][0], cS[nt][1]));
            m1 = fmaxf(m1, fmaxf(cS[nt][2], cS[nt][3]));
        }
        m0 = fmaxf(m0, __shfl_xor_sync(0xffffffffu, m0, 1));
        m0 = fmaxf(m0, __shfl_xor_sync(0xffffffffu, m0, 2));
        m1 = fmaxf(m1, __shfl_xor_sync(0xffffffffu, m1, 1));
        m1 = fmaxf(m1, __shfl_xor_sync(0xffffffffu, m1, 2));
        float s0 = 0.f, s1 = 0.f;
        #pragma unroll
        for (int nt = 0; nt < 8; nt++) {
            cS[nt][0] = __expf((cS[nt][0] - m0) * scale); s0 += cS[nt][0];
            cS[nt][1] = __expf((cS[nt][1] - m0) * scale); s0 += cS[nt][1];
            cS[nt][2] = __expf((cS[nt][2] - m1) * scale); s1 += cS[nt][2];
            cS[nt][3] = __expf((cS[nt][3] - m1) * scale); s1 += cS[nt][3];
        }
        s0 += __shfl_xor_sync(0xffffffffu, s0, 1);
        s0 += __shfl_xor_sync(0xffffffffu, s0, 2);
        s1 += __shfl_xor_sync(0xffffffffu, s1, 1);
        s1 += __shfl_xor_sync(0xffffffffu, s1, 2);
        float i0 = 1.0f / s0, i1 = 1.0f / s1;
        #pragma unroll
        for (int nt = 0; nt < 8; nt++) {
            cS[nt][0] *= i0; cS[nt][1] *= i0;
            cS[nt][2] *= i1; cS[nt][3] *= i1;
        }
    }

    uint32_t ph[4][4], pl[4][4];
    #pragma unroll
    for (int kt = 0; kt < 4; kt++) {
        #pragma unroll
        for (int half = 0; half < 2; half++) {
            int nt = 2 * kt + half;
            __half2 H0 = __floats2half2_rn(cS[nt][0], cS[nt][1]);
            __half2 H1 = __floats2half2_rn(cS[nt][2], cS[nt][3]);
            __half2 L0 = __floats2half2_rn(cS[nt][0] - __half2float(__low2half(H0)),
                                           cS[nt][1] - __half2float(__high2half(H0)));
            __half2 L1 = __floats2half2_rn(cS[nt][2] - __half2float(__low2half(H1)),
                                           cS[nt][3] - __half2float(__high2half(H1)));
            ph[kt][half * 2 + 0] = *(uint32_t*)&H0;
            ph[kt][half * 2 + 1] = *(uint32_t*)&H1;
            pl[kt][half * 2 + 0] = *(uint32_t*)&L0;
            pl[kt][half * 2 + 1] = *(uint32_t*)&L1;
        }
    }

    float cO[4][4];
    #pragma unroll
    for (int nt = 0; nt < 4; nt++)
        #pragma unroll
        for (int c = 0; c < 4; c++) cO[nt][c] = 0.0f;

    #pragma unroll
    for (int kt = 0; kt < 4; kt++) {
        const int vrow = kt * 16 + (lane & 15);
        uint32_t vh2[4][2], vl2[4][2];
        #pragma unroll
        for (int nt = 0; nt < 4; nt++) {
            uint32_t ad = smem_u32(&sVh[vrow][nt * 8]);
            asm volatile("ldmatrix.sync.aligned.m8n8.x2.trans.shared.b16 {%0,%1},[%2];"
                         : "=r"(vh2[nt][0]), "=r"(vh2[nt][1]) : "r"(ad));
            ad = smem_u32(&sVl[vrow][nt * 8]);
            asm volatile("ldmatrix.sync.aligned.m8n8.x2.trans.shared.b16 {%0,%1},[%2];"
                         : "=r"(vl2[nt][0]), "=r"(vl2[nt][1]) : "r"(ad));
        }
        #pragma unroll
        for (int nt = 0; nt < 4; nt++) MMA_F16(cO[nt], ph[kt], vh2[nt]);
        #pragma unroll
        for (int nt = 0; nt < 4; nt++) MMA_F16(cO[nt], pl[kt], vh2[nt]);
        #pragma unroll
        for (int nt = 0; nt < 4; nt++) MMA_F16(cO[nt], ph[kt], vl2[nt]);
    }

    __syncthreads();
    {
        const int g0 = lane >> 2;
        const int c2 = (lane & 3) * 2;
        #pragma unroll
        for (int half = 0; half < 2; half++) {
            int r = warp * 16 + g0 + half * 8;
            #pragma unroll
            for (int nt = 0; nt < 4; nt++) {
                *(__half2*)&sQh[r][nt * 8 + c2] =
                    __floats2half2_rn(cO[nt][half * 2 + 0], cO[nt][half * 2 + 1]);
            }
        }
    }
    __syncthreads();
    {
        #pragma unroll
        for (int j = 0; j < 2; j++) {
            int f = j * 128 + tid;
            int r = f >> 2;
            int ch = f & 3;
            int n = ((wh * 8 + (r >> 3)) << 6) + wc * 8 + (r & 7);
            size_t base = (size_t)(b * 4096 + n) * C_DIM + head * 32 + ch * 8;
            *(uint4*)(ao + base) = *(const uint4*)&sQh[r][ch * 8];
        }
    }
}

// ---------------------------------------------------------------------------
// Host launcher
// ---------------------------------------------------------------------------
extern "C" void kernel_launch(void* const* d_in, const int* in_sizes, int n_in,
                              void* d_out, int out_size)
{
    const float* x      = (const float*)d_in[0];
    const float* W_qkv  = (const float*)d_in[1];
    const float* b_qkv  = (const float*)d_in[2];
    const float* W_proj = (const float*)d_in[3];
    float* out = (float*)d_out;

    __half *qkvh, *qkvl, *ao, *wq, *wp;
    cudaGetSymbolAddress((void**)&qkvh, g_qkvh);
    cudaGetSymbolAddress((void**)&qkvl, g_qkvl);
    cudaGetSymbolAddress((void**)&ao,   g_ao);
    cudaGetSymbolAddress((void**)&wq,   g_wq);
    cudaGetSymbolAddress((void**)&wp,   g_wp);

    cudaFuncSetAttribute(gemm_qkv_kernel,
                         cudaFuncAttributeMaxDynamicSharedMemorySize, FA_DYNSMEM);
    cudaFuncSetAttribute(gemm_proj_kernel,
                         cudaFuncAttributeMaxDynamicSharedMemorySize, PROJ_DYNSMEM);

    // Weight converts (single fp16 plane)
    {
        int w4 = C_DIM * QKV_DIM / 4;
        convert_kernel<<<(w4 + 255) / 256, 256>>>(W_qkv, wq, w4);
        int p4 = C_DIM * C_DIM / 4;
        convert_kernel<<<(p4 + 255) / 256, 256>>>(W_proj, wp, p4);
    }
    // 1) QKV projection (1-term), qkv out as fp16 hi/lo planes
    {
        dim3 grid(QKV_DIM / 128, TOKENS / 128);
        gemm_qkv_kernel<<<grid, 128, FA_DYNSMEM>>>(x, wq, b_qkv,
                                                   qkvh, qkvl, QKV_DIM, C_DIM);
    }
    // 2) Windowed attention (3-term internal), single-plane out
    {
        dim3 grid(1024, 12);
        attn_tc_kernel<<<grid, 128>>>(qkvh, qkvl, ao);
    }
    // 3) Output projection (1-term), fp32 out
    {
        dim3 grid(C_DIM / 128, TOKENS / 128);
        gemm_proj_kernel<<<grid, 128, PROJ_DYNSMEM>>>(ao, wp, out, C_DIM, C_DIM);
    }
}

// round 15
// speedup vs baseline: 2.0753x; 1.1784x over previous
#include <cuda_runtime.h>
#include <cuda_fp16.h>
#include <cstdint>

// x: [16,4096,384] fp32 -> out [16,4096,384] fp32
// 8x8 window attention over 64x64 grid, 12 heads, hd=32.
// Precision: fp16 1-term throughout (single fp16 qkv intermediate).

#define TOKENS   65536
#define C_DIM    384
#define QKV_DIM  1152

__device__ __half  g_qkv[(size_t)TOKENS * QKV_DIM];
__device__ __half  g_ao [(size_t)TOKENS * C_DIM];
__device__ __half  g_wq [(size_t)C_DIM * QKV_DIM];
__device__ __half  g_wp [(size_t)C_DIM * C_DIM];

static __device__ __forceinline__ uint32_t smem_u32(const void* p) {
    return (uint32_t)__cvta_generic_to_shared(p);
}

#define CP_ASYNC16(smem, gptr) \
    asm volatile("cp.async.cg.shared.global [%0], [%1], 16;" :: "r"(smem), "l"(gptr))
#define CP_COMMIT() asm volatile("cp.async.commit_group;" ::: "memory")

#define MMA_F16(d, a, b)                                                       \
    asm volatile(                                                              \
        "mma.sync.aligned.m16n8k16.row.col.f32.f16.f16.f32 "                   \
        "{%0,%1,%2,%3},{%4,%5,%6,%7},{%8,%9},{%0,%1,%2,%3};"                   \
        : "+f"(d[0]), "+f"(d[1]), "+f"(d[2]), "+f"(d[3])                       \
        : "r"(a[0]), "r"(a[1]), "r"(a[2]), "r"(a[3]), "r"(b[0]), "r"(b[1]))

// ---------------------------------------------------------------------------
// fp32 -> fp16 convert (weights)
// ---------------------------------------------------------------------------
__global__ void convert_kernel(const float* __restrict__ in,
                               __half* __restrict__ out16, int n4)
{
    int i = blockIdx.x * blockDim.x + threadIdx.x;
    if (i >= n4) return;
    float4 v = ((const float4*)in)[i];
    __half2* op = (__half2*)out16;
    op[i*2]   = __floats2half2_rn(v.x, v.y);
    op[i*2+1] = __floats2half2_rn(v.z, v.w);
}

// ---------------------------------------------------------------------------
// QKV GEMM (1-term): A fp32 -> fp16 in-kernel; C = A16 @ W16 + bias.
// Output: single fp16 plane (staged coalesced stores).
// smem: AF32 2x18432 @0 | AH 10240 @36864 | B 2x8704 @47104  (=64512)
// ---------------------------------------------------------------------------
#define FA_AF32    0
#define FA_AF32_ST 18432
#define FA_AH      36864
#define FA_B       47104
#define FA_B_ST    8704
#define FA_DYNSMEM 64512

__global__ __launch_bounds__(128, 2)
void gemm_qkv_kernel(const float* __restrict__ A,
                     const __half* __restrict__ B16,
                     const float* __restrict__ bias,
                     __half* __restrict__ C16, int N, int K)
{
    extern __shared__ char smem_raw[];
    const uint32_t sbase = smem_u32(smem_raw);

    const int tid  = threadIdx.x;
    const int lane = tid & 31;
    const int warp = tid >> 5;
    const int wm   = warp >> 1;
    const int wn   = warp & 1;
    const int m0   = blockIdx.y * 128;
    const int n0   = blockIdx.x * 128;
    const int KT   = K / 32;

    float acc[4][8][4];
    #pragma unroll
    for (int mi = 0; mi < 4; mi++)
        #pragma unroll
        for (int ni = 0; ni < 8; ni++)
            #pragma unroll
            for (int c = 0; c < 4; c++) acc[mi][ni][c] = 0.0f;

    uint32_t afo[8]; size_t afg[8];
    #pragma unroll
    for (int j = 0; j < 8; j++) {
        int idx = j * 128 + tid;
        int r = idx >> 3, c = idx & 7;
        afo[j] = (uint32_t)(r * 144 + c * 16);
        afg[j] = (size_t)r * K + c * 4;
    }
    uint32_t bso[4]; size_t bgo[4];
    #pragma unroll
    for (int j = 0; j < 4; j++) {
        int idx = j * 128 + tid;
        int br = idx >> 4, bc = idx & 15;
        bso[j] = (uint32_t)(br * 272 + bc * 16);
        bgo[j] = (size_t)br * N + bc * 8;
    }

    auto load_stage = [&](int kt, int st) {
        uint32_t ab = sbase + FA_AF32 + st * FA_AF32_ST;
        const float* pa = A + (size_t)m0 * K + kt * 32;
        #pragma unroll
        for (int j = 0; j < 8; j++) CP_ASYNC16(ab + afo[j], pa + afg[j]);
        uint32_t bb = sbase + FA_B + st * FA_B_ST;
        const __half* pb = B16 + (size_t)(kt * 32) * N + n0;
        #pragma unroll
        for (int j = 0; j < 4; j++) CP_ASYNC16(bb + bso[j], pb + bgo[j]);
        CP_COMMIT();
    };

    load_stage(0, 0);

    for (int kt = 0; kt < KT; kt++) {
        const int st = kt & 1;
        asm volatile("cp.async.wait_group 0;" ::: "memory");
        __syncthreads();

        if (kt + 1 < KT) load_stage(kt + 1, st ^ 1);

        {
            const float* arow = (const float*)(smem_raw + FA_AF32 + st * FA_AF32_ST
                                               + tid * 144);
            __half* hrow = (__half*)(smem_raw + FA_AH + tid * 80);
            #pragma unroll
            for (int j = 0; j < 8; j++) {
                float4 v = *(const float4*)(arow + j * 4);
                *(__half2*)(hrow + j * 4)     = __floats2half2_rn(v.x, v.y);
                *(__half2*)(hrow + j * 4 + 2) = __floats2half2_rn(v.z, v.w);
            }
        }
        __syncthreads();

        const uint32_t bb = sbase + FA_B + st * FA_B_ST;
        #pragma unroll
        for (int kh = 0; kh < 2; kh++) {
            uint32_t bf[8][2];
            const int brow = kh * 16 + (lane & 15);
            #pragma unroll
            for (int ni = 0; ni < 8; ni++) {
                uint32_t ad = bb + brow * 272 + (uint32_t)((wn * 64 + ni * 8) * 2);
                asm volatile("ldmatrix.sync.aligned.m8n8.x2.trans.shared.b16 {%0,%1},[%2];"
                             : "=r"(bf[ni][0]), "=r"(bf[ni][1]) : "r"(ad));
            }
            #pragma unroll
            for (int mi = 0; mi < 4; mi++) {
                const int arow = wm * 64 + mi * 16 + ((lane >> 3) & 1) * 8 + (lane & 7);
                const int acol = kh * 16 + (lane >> 4) * 8;
                uint32_t Af[4];
                uint32_t ad = sbase + FA_AH + arow * 80 + acol * 2;
                asm volatile("ldmatrix.sync.aligned.m8n8.x4.shared.b16 {%0,%1,%2,%3},[%4];"
                             : "=r"(Af[0]), "=r"(Af[1]), "=r"(Af[2]), "=r"(Af[3]) : "r"(ad));
                #pragma unroll
                for (int ni = 0; ni < 8; ni++) MMA_F16(acc[mi][ni], Af, bf[ni]);
            }
        }
    }

    // Staged epilogue: single fp16 plane, coalesced 16B stores.
    __syncthreads();
    const int rb = wm * 64 + (lane >> 2);
    const int cb = wn * 64 + (lane & 3) * 2;
    #pragma unroll
    for (int ni = 0; ni < 8; ni++) {
        int c = cb + ni * 8;
        float b0 = bias[n0 + c], b1 = bias[n0 + c + 1];
        #pragma unroll
        for (int mi = 0; mi < 4; mi++) {
            #pragma unroll
            for (int h = 0; h < 2; h++) {
                int r = rb + mi * 16 + h * 8;
                *(__half2*)(smem_raw + r * 272 + c * 2) =
                    __floats2half2_rn(acc[mi][ni][h * 2 + 0] + b0,
                                      acc[mi][ni][h * 2 + 1] + b1);
            }
        }
    }
    __syncthreads();
    #pragma unroll
    for (int j = 0; j < 16; j++) {
        int f = j * 128 + tid;
        int r = f >> 4, ch = f & 15;
        uint4 v = *(const uint4*)(smem_raw + r * 272 + ch * 16);
        *(uint4*)(C16 + (size_t)(m0 + r) * N + n0 + ch * 8) = v;
    }
}

// ---------------------------------------------------------------------------
// Proj GEMM (1-term): A fp16 @ W fp16; fp32 out. Unchanged from R14.
// ---------------------------------------------------------------------------
#define P_B  10240
#define P_ST 18944
#define P_NSTAGES 3
#define PROJ_DYNSMEM (P_NSTAGES * P_ST)

__global__ __launch_bounds__(128, 2)
void gemm_proj_kernel(const __half* __restrict__ A16,
                      const __half* __restrict__ B16,
                      float* __restrict__ C, int N, int K)
{
    extern __shared__ char smem_raw[];
    const uint32_t sbase = smem_u32(smem_raw);

    const int tid  = threadIdx.x;
    const int lane = tid & 31;
    const int warp = tid >> 5;
    const int wm   = warp >> 1;
    const int wn   = warp & 1;
    const int m0   = blockIdx.y * 128;
    const int n0   = blockIdx.x * 128;
    const int KT   = K / 32;

    float acc[4][8][4];
    #pragma unroll
    for (int mi = 0; mi < 4; mi++)
        #pragma unroll
        for (int ni = 0; ni < 8; ni++)
            #pragma unroll
            for (int c = 0; c < 4; c++) acc[mi][ni][c] = 0.0f;

    uint32_t aso[4]; size_t ago[4];
    uint32_t bso[4]; size_t bgo[4];
    #pragma unroll
    for (int j = 0; j < 4; j++) {
        int idx = j * 128 + tid;
        int ar = idx >> 2, ac = idx & 3;
        aso[j] = (uint32_t)(ar * 80 + ac * 16);
        ago[j] = (size_t)ar * K + ac * 8;
        int br = idx >> 4, bc = idx & 15;
        bso[j] = (uint32_t)(br * 272 + bc * 16);
        bgo[j] = (size_t)br * N + bc * 8;
    }

    auto load_stage = [&](int kt, int st) {
        uint32_t b = sbase + st * P_ST;
        const __half* pa = A16 + (size_t)m0 * K + kt * 32;
        const __half* pb = B16 + (size_t)(kt * 32) * N + n0;
        #pragma unroll
        for (int j = 0; j < 4; j++) CP_ASYNC16(b + aso[j],       pa + ago[j]);
        #pragma unroll
        for (int j = 0; j < 4; j++) CP_ASYNC16(b + P_B + bso[j], pb + bgo[j]);
        CP_COMMIT();
    };

    load_stage(0, 0);
    load_stage(1, 1);

    int stage = 0;
    for (int kt = 0; kt < KT; kt++) {
        if (kt + 1 < KT) {
            asm volatile("cp.async.wait_group 1;" ::: "memory");
        } else {
            asm volatile("cp.async.wait_group 0;" ::: "memory");
        }
        __syncthreads();

        if (kt + 2 < KT) {
            int st2 = stage + 2; if (st2 >= P_NSTAGES) st2 -= P_NSTAGES;
            load_stage(kt + 2, st2);
        }

        const uint32_t b = sbase + stage * P_ST;
        #pragma unroll
        for (int kh = 0; kh < 2; kh++) {
            uint32_t bf[8][2];
            const int brow = kh * 16 + (lane & 15);
            #pragma unroll
            for (int ni = 0; ni < 8; ni++) {
                uint32_t ad = b + P_B + brow * 272 + (uint32_t)((wn * 64 + ni * 8) * 2);
                asm volatile("ldmatrix.sync.aligned.m8n8.x2.trans.shared.b16 {%0,%1},[%2];"
                             : "=r"(bf[ni][0]), "=r"(bf[ni][1]) : "r"(ad));
            }
            #pragma unroll
            for (int mi = 0; mi < 4; mi++) {
                const int arow = wm * 64 + mi * 16 + ((lane >> 3) & 1) * 8 + (lane & 7);
                const int acol = kh * 16 + (lane >> 4) * 8;
                uint32_t Af[4];
                uint32_t ad = b + arow * 80 + acol * 2;
                asm volatile("ldmatrix.sync.aligned.m8n8.x4.shared.b16 {%0,%1,%2,%3},[%4];"
                             : "=r"(Af[0]), "=r"(Af[1]), "=r"(Af[2]), "=r"(Af[3]) : "r"(ad));
                #pragma unroll
                for (int ni = 0; ni < 8; ni++) MMA_F16(acc[mi][ni], Af, bf[ni]);
            }
        }
        stage++; if (stage >= P_NSTAGES) stage = 0;
    }

    const int rbase = m0 + wm * 64 + (lane >> 2);
    const int cbase = n0 + wn * 64 + (lane & 3) * 2;
    #pragma unroll
    for (int ni = 0; ni < 8; ni++) {
        int c = cbase + ni * 8;
        #pragma unroll
        for (int mi = 0; mi < 4; mi++) {
            int r = rbase + mi * 16;
            *(float2*)(C + (size_t)r * N + c) =
                make_float2(acc[mi][ni][0], acc[mi][ni][1]);
            *(float2*)(C + (size_t)(r + 8) * N + c) =
                make_float2(acc[mi][ni][2], acc[mi][ni][3]);
        }
    }
}

// ---------------------------------------------------------------------------
// Attention: single fp16 qkv plane, 1-term QK and PV.
// ---------------------------------------------------------------------------
__global__ __launch_bounds__(128)
void attn_tc_kernel(const __half* __restrict__ qkv,
                    __half* __restrict__ ao)
{
    __shared__ __half sQ[64][40];
    __shared__ __half sK[64][40];
    __shared__ __half sV[64][40];

    const int wx   = blockIdx.x;
    const int head = blockIdx.y;
    const int b  = wx >> 6;
    const int wi = wx & 63;
    const int wh = wi >> 3;
    const int wc = wi & 7;
    const int tid  = threadIdx.x;
    const int lane = tid & 31;
    const int warp = tid >> 5;

    // cp.async front-end: 3 planes x 64 tokens x 4 chunks = 768 / 128 = 6
    {
        uint32_t dst[3] = { smem_u32(&sQ[0][0]), smem_u32(&sK[0][0]),
                            smem_u32(&sV[0][0]) };
        #pragma unroll
        for (int j = 0; j < 6; j++) {
            int f = j * 128 + tid;          // 0..767
            int m = f >> 8;                 // matrix 0..2
            int q = f & 255;
            int r = q >> 2;                 // token slot
            int c = q & 3;                  // 16B chunk
            int n = ((wh * 8 + (r >> 3)) << 6) + wc * 8 + (r & 7);
            const __half* src = qkv
                + (size_t)(b * 4096 + n) * QKV_DIM + m * 384 + head * 32 + c * 8;
            CP_ASYNC16(dst[m] + (uint32_t)(r * 80 + c * 16), src);
        }
        CP_COMMIT();
    }
    asm volatile("cp.async.wait_group 0;" ::: "memory");
    __syncthreads();

    float cS[8][4];
    #pragma unroll
    for (int nt = 0; nt < 8; nt++)
        #pragma unroll
        for (int c = 0; c < 4; c++) cS[nt][c] = 0.0f;

    #pragma unroll
    for (int kt = 0; kt < 2; kt++) {
        const int arow = warp * 16 + ((lane >> 3) & 1) * 8 + (lane & 7);
        const int acol = kt * 16 + (lane >> 4) * 8;
        uint32_t qf[4];
        uint32_t ad = smem_u32(&sQ[arow][acol]);
        asm volatile("ldmatrix.sync.aligned.m8n8.x4.shared.b16 {%0,%1,%2,%3},[%4];"
                     : "=r"(qf[0]), "=r"(qf[1]), "=r"(qf[2]), "=r"(qf[3]) : "r"(ad));
        #pragma unroll
        for (int nt = 0; nt < 8; nt++) {
            const int brow = nt * 8 + (lane & 7);
            const int bcol = kt * 16 + ((lane >> 3) & 1) * 8;
            uint32_t kf[2];
            uint32_t bd = smem_u32(&sK[brow][bcol]);
            asm volatile("ldmatrix.sync.aligned.m8n8.x2.shared.b16 {%0,%1},[%2];"
                         : "=r"(kf[0]), "=r"(kf[1]) : "r"(bd));
            MMA_F16(cS[nt], qf, kf);
        }
    }

    const float scale = 0.17677669529663687f;
    {
        float m0 = -1e30f, m1 = -1e30f;
        #pragma unroll
        for (int nt = 0; nt < 8; nt++) {
            m0 = fmaxf(m0, fmaxf(cS[nt][0], cS[nt][1]));
            m1 = fmaxf(m1, fmaxf(cS[nt][2], cS[nt][3]));
        }
        m0 = fmaxf(m0, __shfl_xor_sync(0xffffffffu, m0, 1));
        m0 = fmaxf(m0, __shfl_xor_sync(0xffffffffu, m0, 2));
        m1 = fmaxf(m1, __shfl_xor_sync(0xffffffffu, m1, 1));
        m1 = fmaxf(m1, __shfl_xor_sync(0xffffffffu, m1, 2));
        float s0 = 0.f, s1 = 0.f;
        #pragma unroll
        for (int nt = 0; nt < 8; nt++) {
            cS[nt][0] = __expf((cS[nt][0] - m0) * scale); s0 += cS[nt][0];
            cS[nt][1] = __expf((cS[nt][1] - m0) * scale); s0 += cS[nt][1];
            cS[nt][2] = __expf((cS[nt][2] - m1) * scale); s1 += cS[nt][2];
            cS[nt][3] = __expf((cS[nt][3] - m1) * scale); s1 += cS[nt][3];
        }
        s0 += __shfl_xor_sync(0xffffffffu, s0, 1);
        s0 += __shfl_xor_sync(0xffffffffu, s0, 2);
        s1 += __shfl_xor_sync(0xffffffffu, s1, 1);
        s1 += __shfl_xor_sync(0xffffffffu, s1, 2);
        float i0 = 1.0f / s0, i1 = 1.0f / s1;
        #pragma unroll
        for (int nt = 0; nt < 8; nt++) {
            cS[nt][0] *= i0; cS[nt][1] *= i0;
            cS[nt][2] *= i1; cS[nt][3] *= i1;
        }
    }

    // P fragments (single fp16)
    uint32_t pf[4][4];
    #pragma unroll
    for (int kt = 0; kt < 4; kt++) {
        #pragma unroll
        for (int half = 0; half < 2; half++) {
            int nt = 2 * kt + half;
            __half2 H0 = __floats2half2_rn(cS[nt][0], cS[nt][1]);
            __half2 H1 = __floats2half2_rn(cS[nt][2], cS[nt][3]);
            pf[kt][half * 2 + 0] = *(uint32_t*)&H0;
            pf[kt][half * 2 + 1] = *(uint32_t*)&H1;
        }
    }

    float cO[4][4];
    #pragma unroll
    for (int nt = 0; nt < 4; nt++)
        #pragma unroll
        for (int c = 0; c < 4; c++) cO[nt][c] = 0.0f;

    #pragma unroll
    for (int kt = 0; kt < 4; kt++) {
        const int vrow = kt * 16 + (lane & 15);
        #pragma unroll
        for (int nt = 0; nt < 4; nt++) {
            uint32_t vf[2];
            uint32_t ad = smem_u32(&sV[vrow][nt * 8]);
            asm volatile("ldmatrix.sync.aligned.m8n8.x2.trans.shared.b16 {%0,%1},[%2];"
                         : "=r"(vf[0]), "=r"(vf[1]) : "r"(ad));
            MMA_F16(cO[nt], pf[kt], vf);
        }
    }

    // Staged single-plane output (reuse sQ).
    __syncthreads();
    {
        const int g0 = lane >> 2;
        const int c2 = (lane & 3) * 2;
        #pragma unroll
        for (int half = 0; half < 2; half++) {
            int r = warp * 16 + g0 + half * 8;
            #pragma unroll
            for (int nt = 0; nt < 4; nt++) {
                *(__half2*)&sQ[r][nt * 8 + c2] =
                    __floats2half2_rn(cO[nt][half * 2 + 0], cO[nt][half * 2 + 1]);
            }
        }
    }
    __syncthreads();
    {
        #pragma unroll
        for (int j = 0; j < 2; j++) {
            int f = j * 128 + tid;
            int r = f >> 2;
            int ch = f & 3;
            int n = ((wh * 8 + (r >> 3)) << 6) + wc * 8 + (r & 7);
            size_t base = (size_t)(b * 4096 + n) * C_DIM + head * 32 + ch * 8;
            *(uint4*)(ao + base) = *(const uint4*)&sQ[r][ch * 8];
        }
    }
}

// ---------------------------------------------------------------------------
// Host launcher
// ---------------------------------------------------------------------------
extern "C" void kernel_launch(void* const* d_in, const int* in_sizes, int n_in,
                              void* d_out, int out_size)
{
    const float* x      = (const float*)d_in[0];
    const float* W_qkv  = (const float*)d_in[1];
    const float* b_qkv  = (const float*)d_in[2];
    const float* W_proj = (const float*)d_in[3];
    float* out = (float*)d_out;

    __half *qkv, *ao, *wq, *wp;
    cudaGetSymbolAddress((void**)&qkv, g_qkv);
    cudaGetSymbolAddress((void**)&ao,  g_ao);
    cudaGetSymbolAddress((void**)&wq,  g_wq);
    cudaGetSymbolAddress((void**)&wp,  g_wp);

    cudaFuncSetAttribute(gemm_qkv_kernel,
                         cudaFuncAttributeMaxDynamicSharedMemorySize, FA_DYNSMEM);
    cudaFuncSetAttribute(gemm_proj_kernel,
                         cudaFuncAttributeMaxDynamicSharedMemorySize, PROJ_DYNSMEM);

    {
        int w4 = C_DIM * QKV_DIM / 4;
        convert_kernel<<<(w4 + 255) / 256, 256>>>(W_qkv, wq, w4);
        int p4 = C_DIM * C_DIM / 4;
        convert_kernel<<<(p4 + 255) / 256, 256>>>(W_proj, wp, p4);
    }
    {
        dim3 grid(QKV_DIM / 128, TOKENS / 128);
        gemm_qkv_kernel<<<grid, 128, FA_DYNSMEM>>>(x, wq, b_qkv, qkv,
                                                   QKV_DIM, C_DIM);
    }
    {
        dim3 grid(1024, 12);
        attn_tc_kernel<<<grid, 128>>>(qkv, ao);
    }
    {
        dim3 grid(C_DIM / 128, TOKENS / 128);
        gemm_proj_kernel<<<grid, 128, PROJ_DYNSMEM>>>(ao, wp, out, C_DIM, C_DIM);
    }
}